// round 1
// baseline (speedup 1.0000x reference)
#include <cuda_runtime.h>
#include <cuda_bf16.h>
#include <math.h>

#define B_   2
#define L_   2048
#define DM   1024
#define DIP  4384
#define DSSM 2048
#define CD   2304
#define NH   32
#define HD   64
#define DS   128
#define CH   256
#define NC   8

// ---------------- scratch (device globals; no allocation) ----------------
__device__ float g_zx[B_ * L_ * DIP];          // in-proj output (z | xBC | dt_raw)
__device__ float g_xBC[B_ * L_ * CD];          // post-conv+silu (x | B | C)
__device__ float g_dt[B_ * L_ * NH];           // softplus dt
__device__ float g_G[B_ * NC * CH * CH];       // per-chunk C@B^T (head-independent)
__device__ float g_cumA[B_ * NC * NH * CH];    // inclusive cumsum of dt*A per chunk
__device__ float g_states[B_ * NC * NH * HD * DS];
__device__ float g_prev[B_ * NC * NH * HD * DS];
__device__ float g_Y[B_ * L_ * DSSM];
__device__ float g_yn[B_ * L_ * DSSM];

// ---------------- generic fp32 GEMM: C[M,N] = A[M,K] @ B[N,K]^T ----------
__global__ __launch_bounds__(256) void gemm_abt(const float* __restrict__ A,
                                                const float* __restrict__ B,
                                                float* __restrict__ C,
                                                int M, int N, int K) {
    __shared__ float As[16][64];
    __shared__ float Bs[16][64];
    const int m0 = blockIdx.y * 64, n0 = blockIdx.x * 64;
    const int tid = threadIdx.x;
    const int tx = tid & 15, ty = tid >> 4;
    const int lr = tid >> 2, lc = (tid & 3) << 2;

    float4 acc[4];
#pragma unroll
    for (int i = 0; i < 4; i++) acc[i] = make_float4(0.f, 0.f, 0.f, 0.f);

    const float* Aptr = A + (size_t)(m0 + lr) * K + lc;
    const float* Bptr = B + (size_t)(n0 + lr) * K + lc;
    const bool bok = (n0 + lr) < N;

    for (int k0 = 0; k0 < K; k0 += 16) {
        float4 av = *(const float4*)(Aptr + k0);
        float4 bv = bok ? *(const float4*)(Bptr + k0) : make_float4(0.f, 0.f, 0.f, 0.f);
        As[lc + 0][lr] = av.x; As[lc + 1][lr] = av.y; As[lc + 2][lr] = av.z; As[lc + 3][lr] = av.w;
        Bs[lc + 0][lr] = bv.x; Bs[lc + 1][lr] = bv.y; Bs[lc + 2][lr] = bv.z; Bs[lc + 3][lr] = bv.w;
        __syncthreads();
#pragma unroll
        for (int k = 0; k < 16; k++) {
            float4 a = *(const float4*)&As[k][ty * 4];
            float4 b = *(const float4*)&Bs[k][tx * 4];
            acc[0].x += a.x * b.x; acc[0].y += a.x * b.y; acc[0].z += a.x * b.z; acc[0].w += a.x * b.w;
            acc[1].x += a.y * b.x; acc[1].y += a.y * b.y; acc[1].z += a.y * b.z; acc[1].w += a.y * b.w;
            acc[2].x += a.z * b.x; acc[2].y += a.z * b.y; acc[2].z += a.z * b.z; acc[2].w += a.z * b.w;
            acc[3].x += a.w * b.x; acc[3].y += a.w * b.y; acc[3].z += a.w * b.z; acc[3].w += a.w * b.w;
        }
        __syncthreads();
    }
#pragma unroll
    for (int i = 0; i < 4; i++) {
        int m = m0 + ty * 4 + i;
        int n = n0 + tx * 4;
        if (n < N)  // N is a multiple of 4, so whole float4 is in-bounds
            *(float4*)&C[(size_t)m * N + n] = acc[i];
    }
}

// ---------------- tree conv + silu + dt softplus ----------------
__global__ __launch_bounds__(256) void kernel_conv(const int* __restrict__ cidx,
                                                   const float* __restrict__ cw,
                                                   const float* __restrict__ cb,
                                                   const float* __restrict__ dtb) {
    const int bt = blockIdx.x;           // b*L_ + t
    const int b = bt / L_, t = bt - b * L_;
    const int tid = threadIdx.x;

    __shared__ int idx[4];
    if (tid < 4) idx[tid] = cidx[(size_t)b * 4 * L_ + 4 * t + tid];
    __syncthreads();
    const int i0 = idx[0], i1 = idx[1], i2 = idx[2], i3 = idx[3];

    for (int c = tid; c < CD; c += 256) {
        float acc = cb[c];
        const float* w = cw + c * 4;
        if (i0) acc += g_zx[(size_t)(b * L_ + i0 - 1) * DIP + DSSM + c] * w[0];
        if (i1) acc += g_zx[(size_t)(b * L_ + i1 - 1) * DIP + DSSM + c] * w[1];
        if (i2) acc += g_zx[(size_t)(b * L_ + i2 - 1) * DIP + DSSM + c] * w[2];
        if (i3) acc += g_zx[(size_t)(b * L_ + i3 - 1) * DIP + DSSM + c] * w[3];
        g_xBC[(size_t)bt * CD + c] = acc / (1.f + __expf(-acc));   // silu
    }
    if (tid < NH) {
        float x = g_zx[(size_t)bt * DIP + DSSM + CD + tid] + dtb[tid];
        g_dt[bt * NH + tid] = (x > 20.f) ? x : log1pf(expf(x));    // softplus
    }
}

// ---------------- per-(b,c,h) inclusive cumsum of dt*A ----------------
__global__ __launch_bounds__(256) void kernel_cumA(const float* __restrict__ A_log) {
    const int blk = blockIdx.x;                 // (b*NC+c)*NH + h
    const int h = blk & (NH - 1);
    const int bc = blk / NH;
    const int b = bc / NC, c = bc - b * NC;
    const int t = threadIdx.x;
    const float Ah = -expf(A_log[h]);
    const int l = b * L_ + c * CH + t;
    __shared__ float s[CH];
    s[t] = g_dt[l * NH + h] * Ah;
    __syncthreads();
    for (int off = 1; off < CH; off <<= 1) {
        float add = (t >= off) ? s[t - off] : 0.f;
        __syncthreads();
        s[t] += add;
        __syncthreads();
    }
    g_cumA[blk * CH + t] = s[t];
}

// ---------------- G = C @ B^T per (b,chunk): 256x256, K=128 --------------
__global__ void kernel_G() {
    const int bc = blockIdx.z;                 // b*NC + c
    const int t0 = blockIdx.y * 16, s0 = blockIdx.x * 16;
    const int tx = threadIdx.x, ty = threadIdx.y;
    const int tid = ty * 16 + tx;
    __shared__ float Cs[16][129];
    __shared__ float Bs[16][129];
    const int b = bc / NC, c = bc - b * NC;
    const int base_l = b * L_ + c * CH;
    for (int i = tid; i < 16 * 128; i += 256) {
        int row = i >> 7, n = i & 127;
        Cs[row][n] = g_xBC[(size_t)(base_l + t0 + row) * CD + DSSM + DS + n];
        Bs[row][n] = g_xBC[(size_t)(base_l + s0 + row) * CD + DSSM + n];
    }
    __syncthreads();
    float acc = 0.f;
#pragma unroll 8
    for (int n = 0; n < 128; n++) acc += Cs[ty][n] * Bs[tx][n];
    g_G[((size_t)bc * CH + t0 + ty) * CH + s0 + tx] = acc;
}

// ---------------- intra-chunk diagonal: Yd = (G .* L) @ dtx --------------
__global__ __launch_bounds__(256) void kernel_yd() {
    const int blk = blockIdx.x;
    const int h = blk & (NH - 1);
    const int bc = blk / NH;
    const int b = bc / NC, c = bc - b * NC;
    const int t = threadIdx.x;
    __shared__ float cumA_sh[CH];
    __shared__ float dtx_sh[32][HD];
    __shared__ float G_sh[CH][33];

    cumA_sh[t] = g_cumA[blk * CH + t];
    float4 acc[16];
#pragma unroll
    for (int j = 0; j < 16; j++) acc[j] = make_float4(0.f, 0.f, 0.f, 0.f);
    const int base_l = b * L_ + c * CH;
    const float* Gbase = g_G + (size_t)bc * CH * CH;

    for (int s0 = 0; s0 < CH; s0 += 32) {
        for (int i = t; i < 32 * HD; i += 256) {
            int ss = i >> 6, p = i & 63;
            int l = base_l + s0 + ss;
            dtx_sh[ss][p] = g_xBC[(size_t)l * CD + h * HD + p] * g_dt[l * NH + h];
        }
        for (int i = t; i < CH * 32; i += 256) {
            int tt = i >> 5, ss = i & 31;
            G_sh[tt][ss] = Gbase[tt * CH + s0 + ss];
        }
        __syncthreads();
        if (s0 <= t) {
            float cat = cumA_sh[t];
            int smax = t - s0 + 1; if (smax > 32) smax = 32;
            for (int ss = 0; ss < smax; ss++) {
                float w = G_sh[t][ss] * __expf(cat - cumA_sh[s0 + ss]);
                const float4* dp = (const float4*)dtx_sh[ss];
#pragma unroll
                for (int j = 0; j < 16; j++) {
                    float4 v = dp[j];
                    acc[j].x += w * v.x; acc[j].y += w * v.y;
                    acc[j].z += w * v.z; acc[j].w += w * v.w;
                }
            }
        }
        __syncthreads();
    }
    float4* out = (float4*)&g_Y[(size_t)(base_l + t) * DSSM + h * HD];
#pragma unroll
    for (int j = 0; j < 16; j++) out[j] = acc[j];
}

// ---------------- chunk end-states: states[p,n] = sum_s B[s,n]*decay[s]*dtx[s,p]
__global__ __launch_bounds__(256) void kernel_states() {
    const int blk = blockIdx.x;
    const int h = blk & (NH - 1);
    const int bc = blk / NH;
    const int b = bc / NC, c = bc - b * NC;
    const int tid = threadIdx.x;
    const int p = tid >> 2, q = tid & 3;
    __shared__ float cumA_sh[CH];
    __shared__ float decay_sh[CH];
    __shared__ float B_sh[32][132];
    __shared__ float dtx_sh[32][HD];

    cumA_sh[tid] = g_cumA[blk * CH + tid];
    __syncthreads();
    decay_sh[tid] = __expf(cumA_sh[CH - 1] - cumA_sh[tid]);

    float acc[32];
#pragma unroll
    for (int j = 0; j < 32; j++) acc[j] = 0.f;
    const int base_l = b * L_ + c * CH;

    for (int s0 = 0; s0 < CH; s0 += 32) {
        for (int i = tid; i < 32 * DS; i += 256) {
            int ss = i >> 7, n = i & 127;
            B_sh[ss][n] = g_xBC[(size_t)(base_l + s0 + ss) * CD + DSSM + n];
        }
        for (int i = tid; i < 32 * HD; i += 256) {
            int ss = i >> 6, pp = i & 63;
            int l = base_l + s0 + ss;
            dtx_sh[ss][pp] = g_xBC[(size_t)l * CD + h * HD + pp] * g_dt[l * NH + h];
        }
        __syncthreads();
        for (int ss = 0; ss < 32; ss++) {
            float w = decay_sh[s0 + ss] * dtx_sh[ss][p];
            const float4* bp = (const float4*)&B_sh[ss][q * 32];
#pragma unroll
            for (int j4 = 0; j4 < 8; j4++) {
                float4 v = bp[j4];
                acc[4 * j4 + 0] += w * v.x; acc[4 * j4 + 1] += w * v.y;
                acc[4 * j4 + 2] += w * v.z; acc[4 * j4 + 3] += w * v.w;
            }
        }
        __syncthreads();
    }
    float4* out = (float4*)&g_states[(size_t)(blk * HD + p) * DS + q * 32];
#pragma unroll
    for (int j4 = 0; j4 < 8; j4++)
        out[j4] = make_float4(acc[4 * j4], acc[4 * j4 + 1], acc[4 * j4 + 2], acc[4 * j4 + 3]);
}

// ---------------- inter-chunk recurrence (sequential over chunks) --------
__global__ __launch_bounds__(256) void kernel_scan() {
    const int b = blockIdx.x >> 5;
    const int h = blockIdx.x & 31;
    const int tid = threadIdx.x;
    float4 prev[8];
#pragma unroll
    for (int i = 0; i < 8; i++) prev[i] = make_float4(0.f, 0.f, 0.f, 0.f);
    for (int c = 0; c < NC; c++) {
        int blk = (b * NC + c) * NH + h;
        float cd = __expf(g_cumA[blk * CH + CH - 1]);
        const float4* st = (const float4*)&g_states[(size_t)blk * HD * DS];
        float4* pv = (float4*)&g_prev[(size_t)blk * HD * DS];
#pragma unroll
        for (int i = 0; i < 8; i++) {
            float4 s = st[tid + i * 256];
            float4 pr = prev[i];
            pv[tid + i * 256] = pr;
            prev[i] = make_float4(pr.x * cd + s.x, pr.y * cd + s.y,
                                  pr.z * cd + s.z, pr.w * cd + s.w);
        }
    }
}

// ---------------- off-diagonal: Y += exp(cumA[t]) * C @ prev^T + D*x -----
__global__ __launch_bounds__(256) void kernel_yoff(const float* __restrict__ Dv) {
    const int blk = blockIdx.x;
    const int h = blk & (NH - 1);
    const int bc = blk / NH;
    const int b = bc / NC, c = bc - b * NC;
    const int t = threadIdx.x;
    __shared__ float cumA_sh[CH];
    __shared__ float C_sh[CH][33];
    __shared__ float prevT_sh[32][68];

    cumA_sh[t] = g_cumA[blk * CH + t];
    float4 acc[16];
#pragma unroll
    for (int j = 0; j < 16; j++) acc[j] = make_float4(0.f, 0.f, 0.f, 0.f);
    const int base_l = b * L_ + c * CH;
    const float* prev_base = &g_prev[(size_t)blk * HD * DS];

    for (int n0 = 0; n0 < DS; n0 += 32) {
        for (int i = t; i < CH * 32; i += 256) {
            int tt = i >> 5, nn = i & 31;
            C_sh[tt][nn] = g_xBC[(size_t)(base_l + tt) * CD + DSSM + DS + n0 + nn];
        }
        for (int i = t; i < 32 * HD; i += 256) {
            int nn = i & 31, pp = i >> 5;
            prevT_sh[nn][pp] = prev_base[pp * DS + n0 + nn];
        }
        __syncthreads();
        for (int nn = 0; nn < 32; nn++) {
            float cn = C_sh[t][nn];
            const float4* pr = (const float4*)prevT_sh[nn];
#pragma unroll
            for (int j = 0; j < 16; j++) {
                float4 v = pr[j];
                acc[j].x += cn * v.x; acc[j].y += cn * v.y;
                acc[j].z += cn * v.z; acc[j].w += cn * v.w;
            }
        }
        __syncthreads();
    }
    const float eA = __expf(cumA_sh[t]);
    const float Dh = Dv[h];
    const int l = base_l + t;
    const float4* xr = (const float4*)&g_xBC[(size_t)l * CD + h * HD];
    float4* yr = (float4*)&g_Y[(size_t)l * DSSM + h * HD];
#pragma unroll
    for (int j = 0; j < 16; j++) {
        float4 yd = yr[j];
        float4 xv = xr[j];
        yd.x += eA * acc[j].x + Dh * xv.x;
        yd.y += eA * acc[j].y + Dh * xv.y;
        yd.z += eA * acc[j].z + Dh * xv.z;
        yd.w += eA * acc[j].w + Dh * xv.w;
        yr[j] = yd;
    }
}

// ---------------- gated RMSNorm ----------------
__global__ __launch_bounds__(256) void kernel_norm(const float* __restrict__ nw) {
    const int row = blockIdx.x;
    const int tid = threadIdx.x;
    const float* y = &g_Y[(size_t)row * DSSM];
    const float* z = &g_zx[(size_t)row * DIP];  // z = first DSSM cols
    float v[8];
    float sum = 0.f;
#pragma unroll
    for (int i = 0; i < 8; i++) {
        int cc = tid + i * 256;
        float zz = z[cc];
        float vv = y[cc] * (zz / (1.f + __expf(-zz)));
        v[i] = vv;
        sum += vv * vv;
    }
    __shared__ float red[256];
    red[tid] = sum;
    __syncthreads();
    for (int off = 128; off; off >>= 1) {
        if (tid < off) red[tid] += red[tid + off];
        __syncthreads();
    }
    const float scale = rsqrtf(red[0] * (1.f / DSSM) + 1e-5f);
#pragma unroll
    for (int i = 0; i < 8; i++) {
        int cc = tid + i * 256;
        g_yn[(size_t)row * DSSM + cc] = v[i] * scale * nw[cc];
    }
}

// ---------------- launch ----------------
extern "C" void kernel_launch(void* const* d_in, const int* in_sizes, int n_in,
                              void* d_out, int out_size) {
    const float* u     = (const float*)d_in[0];
    const int*   cidx  = (const int*)d_in[1];
    const float* W_in  = (const float*)d_in[2];
    const float* cw    = (const float*)d_in[3];
    const float* cb    = (const float*)d_in[4];
    const float* dtb   = (const float*)d_in[5];
    const float* A_log = (const float*)d_in[6];
    const float* Dv    = (const float*)d_in[7];
    const float* nw    = (const float*)d_in[8];
    const float* W_out = (const float*)d_in[9];
    float* out = (float*)d_out;

    float *zx_p, *yn_p;
    cudaGetSymbolAddress((void**)&zx_p, g_zx);
    cudaGetSymbolAddress((void**)&yn_p, g_yn);

    // 1) zxbcdt = u @ W_in^T   (M=4096, N=4384, K=1024)
    gemm_abt<<<dim3((DIP + 63) / 64, (B_ * L_) / 64), 256>>>(u, W_in, zx_p, B_ * L_, DIP, DM);
    // 2) tree conv + silu + dt softplus
    kernel_conv<<<B_ * L_, 256>>>(cidx, cw, cb, dtb);
    // 3) cumsum(dt*A) per chunk/head
    kernel_cumA<<<B_ * NC * NH, 256>>>(A_log);
    // 4) G = C@B^T per (b,chunk)
    kernel_G<<<dim3(CH / 16, CH / 16, B_ * NC), dim3(16, 16)>>>();
    // 5) intra-chunk Yd
    kernel_yd<<<B_ * NC * NH, 256>>>();
    // 6) chunk end-states
    kernel_states<<<B_ * NC * NH, 256>>>();
    // 7) inter-chunk scan
    kernel_scan<<<B_ * NH, 256>>>();
    // 8) off-diagonal + D*x
    kernel_yoff<<<B_ * NC * NH, 256>>>(Dv);
    // 9) gated RMSNorm
    kernel_norm<<<B_ * L_, 256>>>(nw);
    // 10) out = yn @ W_out^T  (M=4096, N=1024, K=2048)
    gemm_abt<<<dim3(DM / 64, (B_ * L_) / 64), 256>>>(yn_p, W_out, out, B_ * L_, DM, DSSM);
}

// round 3
// speedup vs baseline: 1.5898x; 1.5898x over previous
#include <cuda_runtime.h>
#include <cuda_bf16.h>
#include <math.h>
#include <stdint.h>

#define B_   2
#define L_   2048
#define DM   1024
#define DIP  4384
#define DSSM 2048
#define CD   2304
#define NH   32
#define HD   64
#define DS   128
#define CH   256
#define NC   8

// ---------------- scratch (device globals; no allocation) ----------------
__device__ float g_zx[B_ * L_ * DIP];          // in-proj output (z | xBC | dt_raw)
__device__ float g_xBC[B_ * L_ * CD];          // post-conv+silu (x | B | C)
__device__ float g_dt[B_ * L_ * NH];           // softplus dt
__device__ float g_G[B_ * NC * CH * CH];       // per-chunk C@B^T (head-independent)
__device__ float g_cumA[B_ * NC * NH * CH];    // inclusive cumsum of dt*A per chunk
__device__ float g_states[B_ * NC * NH * HD * DS];
__device__ float g_prev[B_ * NC * NH * HD * DS];
__device__ float g_Y[B_ * L_ * DSSM];

// bf16 split-precision operand buffers for tensor-core GEMMs
__device__ __nv_bfloat16 g_uh[B_ * L_ * DM];
__device__ __nv_bfloat16 g_ul[B_ * L_ * DM];
__device__ __nv_bfloat16 g_wih[DIP * DM];
__device__ __nv_bfloat16 g_wil[DIP * DM];
__device__ __nv_bfloat16 g_woh[DM * DSSM];
__device__ __nv_bfloat16 g_wol[DM * DSSM];
__device__ __nv_bfloat16 g_ynh[B_ * L_ * DSSM];
__device__ __nv_bfloat16 g_ynl[B_ * L_ * DSSM];

// ---------------- warp-level MMA helpers (arch-neutral PTX) ----------------
__device__ __forceinline__ uint32_t smem_u32(const void* p) {
    uint32_t a;
    asm("{ .reg .u64 t; cvta.to.shared.u64 t, %1; cvt.u32.u64 %0, t; }" : "=r"(a) : "l"(p));
    return a;
}
__device__ __forceinline__ void ldm4(uint32_t* r, uint32_t addr) {
    asm volatile("ldmatrix.sync.aligned.m8n8.x4.shared.b16 {%0,%1,%2,%3}, [%4];"
                 : "=r"(r[0]), "=r"(r[1]), "=r"(r[2]), "=r"(r[3]) : "r"(addr));
}
__device__ __forceinline__ void mma16816(float* d, const uint32_t* a,
                                         uint32_t b0, uint32_t b1) {
    asm volatile(
        "mma.sync.aligned.m16n8k16.row.col.f32.bf16.bf16.f32 "
        "{%0,%1,%2,%3}, {%4,%5,%6,%7}, {%8,%9}, {%0,%1,%2,%3};"
        : "+f"(d[0]), "+f"(d[1]), "+f"(d[2]), "+f"(d[3])
        : "r"(a[0]), "r"(a[1]), "r"(a[2]), "r"(a[3]), "r"(b0), "r"(b1));
}
__device__ __forceinline__ void cpasync16(uint32_t dst, const void* src, int sz) {
    asm volatile("cp.async.cg.shared.global [%0], [%1], 16, %2;"
                 :: "r"(dst), "l"(src), "r"(sz) : "memory");
}
#define CP_COMMIT() asm volatile("cp.async.commit_group;" ::: "memory")
#define CP_WAIT0()  asm volatile("cp.async.wait_group 0;" ::: "memory")
#define CP_WAIT1()  asm volatile("cp.async.wait_group 1;" ::: "memory")

// ---------------- fp32 -> bf16 hi/lo split ----------------
__global__ __launch_bounds__(256) void split_bf16(const float* __restrict__ src,
                                                  __nv_bfloat16* __restrict__ hi,
                                                  __nv_bfloat16* __restrict__ lo,
                                                  int n4) {
    int i = blockIdx.x * 256 + threadIdx.x;
    if (i >= n4) return;
    float4 v = ((const float4*)src)[i];
    __nv_bfloat16 h0 = __float2bfloat16(v.x), h1 = __float2bfloat16(v.y);
    __nv_bfloat16 h2 = __float2bfloat16(v.z), h3 = __float2bfloat16(v.w);
    __nv_bfloat16 l0 = __float2bfloat16(v.x - __bfloat162float(h0));
    __nv_bfloat16 l1 = __float2bfloat16(v.y - __bfloat162float(h1));
    __nv_bfloat16 l2 = __float2bfloat16(v.z - __bfloat162float(h2));
    __nv_bfloat16 l3 = __float2bfloat16(v.w - __bfloat162float(h3));
    __nv_bfloat162 ph0{h0, h1}, ph1{h2, h3}, pl0{l0, l1}, pl1{l2, l3};
    ((__nv_bfloat162*)hi)[2 * i + 0] = ph0;
    ((__nv_bfloat162*)hi)[2 * i + 1] = ph1;
    ((__nv_bfloat162*)lo)[2 * i + 0] = pl0;
    ((__nv_bfloat162*)lo)[2 * i + 1] = pl1;
}

// ---------------- split-bf16 HMMA GEMM: C[M,N] = A[M,K] @ B[N,K]^T --------
// 128x128 CTA tile, 256 thr (warps 4m x 2n, 32x64 each), k-tile 32,
// double-buffered cp.async smem, ldmatrix.x4 frags, 3 MMAs per frag-pair.
// smem per stage: Ahi 8K | Alo 8K | Bhi 8K | Blo 8K = 32KB; 2 stages = 64KB.
#define GM_SMEM 65536
// chunk swizzle for 64-byte rows: conflict-free 8-row ldmatrix gathers
#define CSWZ(r, c) (((c) ^ (((r) >> 1) & 3)) << 4)

__global__ __launch_bounds__(256, 1) void gemm_mma(const __nv_bfloat16* __restrict__ Ah,
                                                   const __nv_bfloat16* __restrict__ Al,
                                                   const __nv_bfloat16* __restrict__ Bh,
                                                   const __nv_bfloat16* __restrict__ Bl,
                                                   float* __restrict__ C,
                                                   int M, int N, int K) {
    extern __shared__ __align__(1024) char sm[];
    const int tid = threadIdx.x;
    const int m0 = blockIdx.y * 128, n0 = blockIdx.x * 128;
    const uint32_t sb0 = smem_u32(sm);
    const int warp = tid >> 5, lane = tid & 31;
    const int warp_m = warp & 3, warp_n = warp >> 2;
    const int KT = K >> 5;

    float acc[2][8][4];
#pragma unroll
    for (int a = 0; a < 2; a++)
#pragma unroll
        for (int b = 0; b < 8; b++)
#pragma unroll
            for (int c = 0; c < 4; c++) acc[a][b][c] = 0.f;

    // ---- stage loader ----
    auto load_stage = [&](int kt, int s) {
        const uint32_t sb = sb0 + s * 32768;
        const int k0 = kt << 5;
#pragma unroll
        for (int ii = 0; ii < 2; ii++) {
            const int i = tid + ii * 256;
            const int r = i >> 2, c = i & 3;
            const uint32_t sw = (uint32_t)(r * 64) + CSWZ(r, c);
            const size_t ga = (size_t)(m0 + r) * K + k0 + c * 8;
            cpasync16(sb + sw, Ah + ga, 16);
            cpasync16(sb + 8192 + sw, Al + ga, 16);
            const int rb = (n0 + r < N) ? (n0 + r) : (N - 1);
            const int bs = (n0 + r < N) ? 16 : 0;
            const size_t gb = (size_t)rb * K + k0 + c * 8;
            cpasync16(sb + 16384 + sw, Bh + gb, bs);
            cpasync16(sb + 24576 + sw, Bl + gb, bs);
        }
    };

    load_stage(0, 0);
    CP_COMMIT();

    const int lrow = (lane & 7) + ((lane >> 3) & 1) * 8;
    const int lhalf = lane >> 4;

    for (int kt = 0; kt < KT; kt++) {
        if (kt + 1 < KT) {
            load_stage(kt + 1, (kt + 1) & 1);
            CP_COMMIT();
            CP_WAIT1();
        } else {
            CP_WAIT0();
        }
        __syncthreads();

        const uint32_t sb = sb0 + (kt & 1) * 32768;
#pragma unroll
        for (int ki = 0; ki < 2; ki++) {
            const int chunk = ki * 2 + lhalf;
            uint32_t ah[2][4], al[2][4];
#pragma unroll
            for (int mi = 0; mi < 2; mi++) {
                const int r = warp_m * 32 + mi * 16 + lrow;
                const uint32_t off = (uint32_t)(r * 64) + CSWZ(r, chunk);
                ldm4(ah[mi], sb + off);
                ldm4(al[mi], sb + 8192 + off);
            }
            uint32_t bh[4][4], bl[4][4];
#pragma unroll
            for (int nj = 0; nj < 4; nj++) {
                const int r = warp_n * 64 + nj * 16 + lrow;
                const uint32_t off = (uint32_t)(r * 64) + CSWZ(r, chunk);
                ldm4(bh[nj], sb + 16384 + off);
                ldm4(bl[nj], sb + 24576 + off);
            }
#pragma unroll
            for (int mi = 0; mi < 2; mi++)
#pragma unroll
                for (int nj = 0; nj < 8; nj++) {
                    const int g = nj >> 1, h = nj & 1;
                    mma16816(acc[mi][nj], ah[mi], bh[g][h], bh[g][h + 2]);
                    mma16816(acc[mi][nj], ah[mi], bl[g][h], bl[g][h + 2]);
                    mma16816(acc[mi][nj], al[mi], bh[g][h], bh[g][h + 2]);
                }
        }
        __syncthreads();
    }

    // ---- epilogue ----
#pragma unroll
    for (int mi = 0; mi < 2; mi++)
#pragma unroll
        for (int nj = 0; nj < 8; nj++) {
            const int row = m0 + warp_m * 32 + mi * 16 + (lane >> 2);
            const int col = n0 + warp_n * 64 + nj * 8 + (lane & 3) * 2;
            if (col < N) {
                float2 v0 = make_float2(acc[mi][nj][0], acc[mi][nj][1]);
                float2 v1 = make_float2(acc[mi][nj][2], acc[mi][nj][3]);
                *(float2*)&C[(size_t)row * N + col] = v0;
                *(float2*)&C[(size_t)(row + 8) * N + col] = v1;
            }
        }
}

// ---------------- tree conv + silu + dt softplus ----------------
__global__ __launch_bounds__(256) void kernel_conv(const int* __restrict__ cidx,
                                                   const float* __restrict__ cw,
                                                   const float* __restrict__ cb,
                                                   const float* __restrict__ dtb) {
    const int bt = blockIdx.x;           // b*L_ + t
    const int b = bt / L_, t = bt - b * L_;
    const int tid = threadIdx.x;

    __shared__ int idx[4];
    if (tid < 4) idx[tid] = cidx[(size_t)b * 4 * L_ + 4 * t + tid];
    __syncthreads();
    const int i0 = idx[0], i1 = idx[1], i2 = idx[2], i3 = idx[3];

    for (int c = tid; c < CD; c += 256) {
        float acc = cb[c];
        const float* w = cw + c * 4;
        if (i0) acc += g_zx[(size_t)(b * L_ + i0 - 1) * DIP + DSSM + c] * w[0];
        if (i1) acc += g_zx[(size_t)(b * L_ + i1 - 1) * DIP + DSSM + c] * w[1];
        if (i2) acc += g_zx[(size_t)(b * L_ + i2 - 1) * DIP + DSSM + c] * w[2];
        if (i3) acc += g_zx[(size_t)(b * L_ + i3 - 1) * DIP + DSSM + c] * w[3];
        g_xBC[(size_t)bt * CD + c] = acc / (1.f + __expf(-acc));   // silu
    }
    if (tid < NH) {
        float x = g_zx[(size_t)bt * DIP + DSSM + CD + tid] + dtb[tid];
        g_dt[bt * NH + tid] = (x > 20.f) ? x : log1pf(expf(x));    // softplus
    }
}

// ---------------- per-(b,c,h) inclusive cumsum of dt*A ----------------
__global__ __launch_bounds__(256) void kernel_cumA(const float* __restrict__ A_log) {
    const int blk = blockIdx.x;                 // (b*NC+c)*NH + h
    const int h = blk & (NH - 1);
    const int bc = blk / NH;
    const int b = bc / NC, c = bc - b * NC;
    const int t = threadIdx.x;
    const float Ah = -expf(A_log[h]);
    const int l = b * L_ + c * CH + t;
    __shared__ float s[CH];
    s[t] = g_dt[l * NH + h] * Ah;
    __syncthreads();
    for (int off = 1; off < CH; off <<= 1) {
        float add = (t >= off) ? s[t - off] : 0.f;
        __syncthreads();
        s[t] += add;
        __syncthreads();
    }
    g_cumA[blk * CH + t] = s[t];
}

// ---------------- G = C @ B^T per (b,chunk): 256x256, K=128 --------------
__global__ void kernel_G() {
    const int bc = blockIdx.z;                 // b*NC + c
    const int t0 = blockIdx.y * 16, s0 = blockIdx.x * 16;
    const int tx = threadIdx.x, ty = threadIdx.y;
    const int tid = ty * 16 + tx;
    __shared__ float Cs[16][129];
    __shared__ float Bs[16][129];
    const int b = bc / NC, c = bc - b * NC;
    const int base_l = b * L_ + c * CH;
    for (int i = tid; i < 16 * 128; i += 256) {
        int row = i >> 7, n = i & 127;
        Cs[row][n] = g_xBC[(size_t)(base_l + t0 + row) * CD + DSSM + DS + n];
        Bs[row][n] = g_xBC[(size_t)(base_l + s0 + row) * CD + DSSM + n];
    }
    __syncthreads();
    float acc = 0.f;
#pragma unroll 8
    for (int n = 0; n < 128; n++) acc += Cs[ty][n] * Bs[tx][n];
    g_G[((size_t)bc * CH + t0 + ty) * CH + s0 + tx] = acc;
}

// ---------------- intra-chunk diagonal: Yd = (G .* L) @ dtx --------------
__global__ __launch_bounds__(256) void kernel_yd() {
    const int blk = blockIdx.x;
    const int h = blk & (NH - 1);
    const int bc = blk / NH;
    const int b = bc / NC, c = bc - b * NC;
    const int t = threadIdx.x;
    __shared__ float cumA_sh[CH];
    __shared__ float dtx_sh[32][HD];
    __shared__ float G_sh[CH][33];

    cumA_sh[t] = g_cumA[blk * CH + t];
    float4 acc[16];
#pragma unroll
    for (int j = 0; j < 16; j++) acc[j] = make_float4(0.f, 0.f, 0.f, 0.f);
    const int base_l = b * L_ + c * CH;
    const float* Gbase = g_G + (size_t)bc * CH * CH;

    for (int s0 = 0; s0 < CH; s0 += 32) {
        for (int i = t; i < 32 * HD; i += 256) {
            int ss = i >> 6, p = i & 63;
            int l = base_l + s0 + ss;
            dtx_sh[ss][p] = g_xBC[(size_t)l * CD + h * HD + p] * g_dt[l * NH + h];
        }
        for (int i = t; i < CH * 32; i += 256) {
            int tt = i >> 5, ss = i & 31;
            G_sh[tt][ss] = Gbase[tt * CH + s0 + ss];
        }
        __syncthreads();
        if (s0 <= t) {
            float cat = cumA_sh[t];
            int smax = t - s0 + 1; if (smax > 32) smax = 32;
            for (int ss = 0; ss < smax; ss++) {
                float w = G_sh[t][ss] * __expf(cat - cumA_sh[s0 + ss]);
                const float4* dp = (const float4*)dtx_sh[ss];
#pragma unroll
                for (int j = 0; j < 16; j++) {
                    float4 v = dp[j];
                    acc[j].x += w * v.x; acc[j].y += w * v.y;
                    acc[j].z += w * v.z; acc[j].w += w * v.w;
                }
            }
        }
        __syncthreads();
    }
    float4* out = (float4*)&g_Y[(size_t)(base_l + t) * DSSM + h * HD];
#pragma unroll
    for (int j = 0; j < 16; j++) out[j] = acc[j];
}

// ---------------- chunk end-states: states[p,n] = sum_s B[s,n]*decay[s]*dtx[s,p]
__global__ __launch_bounds__(256) void kernel_states() {
    const int blk = blockIdx.x;
    const int h = blk & (NH - 1);
    const int bc = blk / NH;
    const int b = bc / NC, c = bc - b * NC;
    const int tid = threadIdx.x;
    const int p = tid >> 2, q = tid & 3;
    __shared__ float cumA_sh[CH];
    __shared__ float decay_sh[CH];
    __shared__ float B_sh[32][132];
    __shared__ float dtx_sh[32][HD];

    cumA_sh[tid] = g_cumA[blk * CH + tid];
    __syncthreads();
    decay_sh[tid] = __expf(cumA_sh[CH - 1] - cumA_sh[tid]);

    float acc[32];
#pragma unroll
    for (int j = 0; j < 32; j++) acc[j] = 0.f;
    const int base_l = b * L_ + c * CH;

    for (int s0 = 0; s0 < CH; s0 += 32) {
        for (int i = tid; i < 32 * DS; i += 256) {
            int ss = i >> 7, n = i & 127;
            B_sh[ss][n] = g_xBC[(size_t)(base_l + s0 + ss) * CD + DSSM + n];
        }
        for (int i = tid; i < 32 * HD; i += 256) {
            int ss = i >> 6, pp = i & 63;
            int l = base_l + s0 + ss;
            dtx_sh[ss][pp] = g_xBC[(size_t)l * CD + h * HD + pp] * g_dt[l * NH + h];
        }
        __syncthreads();
        for (int ss = 0; ss < 32; ss++) {
            float w = decay_sh[s0 + ss] * dtx_sh[ss][p];
            const float4* bp = (const float4*)&B_sh[ss][q * 32];
#pragma unroll
            for (int j4 = 0; j4 < 8; j4++) {
                float4 v = bp[j4];
                acc[4 * j4 + 0] += w * v.x; acc[4 * j4 + 1] += w * v.y;
                acc[4 * j4 + 2] += w * v.z; acc[4 * j4 + 3] += w * v.w;
            }
        }
        __syncthreads();
    }
    float4* out = (float4*)&g_states[(size_t)(blk * HD + p) * DS + q * 32];
#pragma unroll
    for (int j4 = 0; j4 < 8; j4++)
        out[j4] = make_float4(acc[4 * j4], acc[4 * j4 + 1], acc[4 * j4 + 2], acc[4 * j4 + 3]);
}

// ---------------- inter-chunk recurrence (sequential over chunks) --------
__global__ __launch_bounds__(256) void kernel_scan() {
    const int b = blockIdx.x >> 5;
    const int h = blockIdx.x & 31;
    const int tid = threadIdx.x;
    float4 prev[8];
#pragma unroll
    for (int i = 0; i < 8; i++) prev[i] = make_float4(0.f, 0.f, 0.f, 0.f);
    for (int c = 0; c < NC; c++) {
        int blk = (b * NC + c) * NH + h;
        float cd = __expf(g_cumA[blk * CH + CH - 1]);
        const float4* st = (const float4*)&g_states[(size_t)blk * HD * DS];
        float4* pv = (float4*)&g_prev[(size_t)blk * HD * DS];
#pragma unroll
        for (int i = 0; i < 8; i++) {
            float4 s = st[tid + i * 256];
            float4 pr = prev[i];
            pv[tid + i * 256] = pr;
            prev[i] = make_float4(pr.x * cd + s.x, pr.y * cd + s.y,
                                  pr.z * cd + s.z, pr.w * cd + s.w);
        }
    }
}

// ---------------- off-diagonal: Y += exp(cumA[t]) * C @ prev^T + D*x -----
__global__ __launch_bounds__(256) void kernel_yoff(const float* __restrict__ Dv) {
    const int blk = blockIdx.x;
    const int h = blk & (NH - 1);
    const int bc = blk / NH;
    const int b = bc / NC, c = bc - b * NC;
    const int t = threadIdx.x;
    __shared__ float cumA_sh[CH];
    __shared__ float C_sh[CH][33];
    __shared__ float prevT_sh[32][68];

    cumA_sh[t] = g_cumA[blk * CH + t];
    float4 acc[16];
#pragma unroll
    for (int j = 0; j < 16; j++) acc[j] = make_float4(0.f, 0.f, 0.f, 0.f);
    const int base_l = b * L_ + c * CH;
    const float* prev_base = &g_prev[(size_t)blk * HD * DS];

    for (int n0 = 0; n0 < DS; n0 += 32) {
        for (int i = t; i < CH * 32; i += 256) {
            int tt = i >> 5, nn = i & 31;
            C_sh[tt][nn] = g_xBC[(size_t)(base_l + tt) * CD + DSSM + DS + n0 + nn];
        }
        for (int i = t; i < 32 * HD; i += 256) {
            int nn = i & 31, pp = i >> 5;
            prevT_sh[nn][pp] = prev_base[pp * DS + n0 + nn];
        }
        __syncthreads();
        for (int nn = 0; nn < 32; nn++) {
            float cn = C_sh[t][nn];
            const float4* pr = (const float4*)prevT_sh[nn];
#pragma unroll
            for (int j = 0; j < 16; j++) {
                float4 v = pr[j];
                acc[j].x += cn * v.x; acc[j].y += cn * v.y;
                acc[j].z += cn * v.z; acc[j].w += cn * v.w;
            }
        }
        __syncthreads();
    }
    const float eA = __expf(cumA_sh[t]);
    const float Dh = Dv[h];
    const int l = base_l + t;
    const float4* xr = (const float4*)&g_xBC[(size_t)l * CD + h * HD];
    float4* yr = (float4*)&g_Y[(size_t)l * DSSM + h * HD];
#pragma unroll
    for (int j = 0; j < 16; j++) {
        float4 yd = yr[j];
        float4 xv = xr[j];
        yd.x += eA * acc[j].x + Dh * xv.x;
        yd.y += eA * acc[j].y + Dh * xv.y;
        yd.z += eA * acc[j].z + Dh * xv.z;
        yd.w += eA * acc[j].w + Dh * xv.w;
        yr[j] = yd;
    }
}

// ---------------- gated RMSNorm -> bf16 hi/lo ----------------
__global__ __launch_bounds__(256) void kernel_norm(const float* __restrict__ nw) {
    const int row = blockIdx.x;
    const int tid = threadIdx.x;
    const float* y = &g_Y[(size_t)row * DSSM];
    const float* z = &g_zx[(size_t)row * DIP];  // z = first DSSM cols
    float v[8];
    float sum = 0.f;
#pragma unroll
    for (int i = 0; i < 8; i++) {
        int cc = tid + i * 256;
        float zz = z[cc];
        float vv = y[cc] * (zz / (1.f + __expf(-zz)));
        v[i] = vv;
        sum += vv * vv;
    }
    __shared__ float red[256];
    red[tid] = sum;
    __syncthreads();
    for (int off = 128; off; off >>= 1) {
        if (tid < off) red[tid] += red[tid + off];
        __syncthreads();
    }
    const float scale = rsqrtf(red[0] * (1.f / DSSM) + 1e-5f);
#pragma unroll
    for (int i = 0; i < 8; i++) {
        int cc = tid + i * 256;
        float o = v[i] * scale * nw[cc];
        __nv_bfloat16 h = __float2bfloat16(o);
        g_ynh[(size_t)row * DSSM + cc] = h;
        g_ynl[(size_t)row * DSSM + cc] = __float2bfloat16(o - __bfloat162float(h));
    }
}

// ---------------- launch ----------------
extern "C" void kernel_launch(void* const* d_in, const int* in_sizes, int n_in,
                              void* d_out, int out_size) {
    const float* u     = (const float*)d_in[0];
    const int*   cidx  = (const int*)d_in[1];
    const float* W_in  = (const float*)d_in[2];
    const float* cw    = (const float*)d_in[3];
    const float* cb    = (const float*)d_in[4];
    const float* dtb   = (const float*)d_in[5];
    const float* A_log = (const float*)d_in[6];
    const float* Dv    = (const float*)d_in[7];
    const float* nw    = (const float*)d_in[8];
    const float* W_out = (const float*)d_in[9];
    float* out = (float*)d_out;

    float* zx_p;
    __nv_bfloat16 *uh, *ul, *wih, *wil, *woh, *wol, *ynh, *ynl;
    cudaGetSymbolAddress((void**)&zx_p, g_zx);
    cudaGetSymbolAddress((void**)&uh, g_uh);
    cudaGetSymbolAddress((void**)&ul, g_ul);
    cudaGetSymbolAddress((void**)&wih, g_wih);
    cudaGetSymbolAddress((void**)&wil, g_wil);
    cudaGetSymbolAddress((void**)&woh, g_woh);
    cudaGetSymbolAddress((void**)&wol, g_wol);
    cudaGetSymbolAddress((void**)&ynh, g_ynh);
    cudaGetSymbolAddress((void**)&ynl, g_ynl);

    cudaFuncSetAttribute(gemm_mma, cudaFuncAttributeMaxDynamicSharedMemorySize, GM_SMEM);

    // 0) split fp32 -> bf16 hi/lo
    {
        int n4;
        n4 = (B_ * L_ * DM) / 4;
        split_bf16<<<(n4 + 255) / 256, 256>>>(u, uh, ul, n4);
        n4 = (DIP * DM) / 4;
        split_bf16<<<(n4 + 255) / 256, 256>>>(W_in, wih, wil, n4);
        n4 = (DM * DSSM) / 4;
        split_bf16<<<(n4 + 255) / 256, 256>>>(W_out, woh, wol, n4);
    }
    // 1) zxbcdt = u @ W_in^T   (M=4096, N=4384, K=1024) on HMMA
    gemm_mma<<<dim3((DIP + 127) / 128, (B_ * L_) / 128), 256, GM_SMEM>>>(
        uh, ul, wih, wil, zx_p, B_ * L_, DIP, DM);
    // 2) tree conv + silu + dt softplus
    kernel_conv<<<B_ * L_, 256>>>(cidx, cw, cb, dtb);
    // 3) cumsum(dt*A) per chunk/head
    kernel_cumA<<<B_ * NC * NH, 256>>>(A_log);
    // 4) G = C@B^T per (b,chunk)
    kernel_G<<<dim3(CH / 16, CH / 16, B_ * NC), dim3(16, 16)>>>();
    // 5) intra-chunk Yd
    kernel_yd<<<B_ * NC * NH, 256>>>();
    // 6) chunk end-states
    kernel_states<<<B_ * NC * NH, 256>>>();
    // 7) inter-chunk scan
    kernel_scan<<<B_ * NH, 256>>>();
    // 8) off-diagonal + D*x
    kernel_yoff<<<B_ * NC * NH, 256>>>(Dv);
    // 9) gated RMSNorm -> bf16 hi/lo
    kernel_norm<<<B_ * L_, 256>>>(nw);
    // 10) out = yn @ W_out^T  (M=4096, N=1024, K=2048) on HMMA
    gemm_mma<<<dim3(DM / 128, (B_ * L_) / 128), 256, GM_SMEM>>>(
        ynh, ynl, woh, wol, out, B_ * L_, DM, DSSM);
}

// round 4
// speedup vs baseline: 2.3728x; 1.4925x over previous
#include <cuda_runtime.h>
#include <cuda_bf16.h>
#include <math.h>
#include <stdint.h>

#define B_   2
#define L_   2048
#define DM   1024
#define DIP  4384
#define DSSM 2048
#define CD   2304
#define NH   32
#define HD   64
#define DS   128
#define CH   256
#define NC   8

// ---------------- scratch (device globals; no allocation) ----------------
__device__ float g_zx[B_ * L_ * DIP];          // in-proj output (z | xBC | dt_raw)
__device__ float g_xBC[B_ * L_ * CD];          // post-conv+silu (x | B | C)
__device__ float g_dt[B_ * L_ * NH];           // softplus dt
__device__ float g_G[B_ * NC * CH * CH];       // per-chunk C@B^T (head-independent)
__device__ float g_cumA[B_ * NC * NH * CH];    // inclusive cumsum of dt*A per chunk
__device__ float g_states[B_ * NC * NH * HD * DS];
__device__ float g_prev[B_ * NC * NH * HD * DS];
__device__ float g_Y[B_ * L_ * DSSM];

// bf16 split-precision operand buffers for tensor-core GEMMs
__device__ __nv_bfloat16 g_uh[B_ * L_ * DM];
__device__ __nv_bfloat16 g_ul[B_ * L_ * DM];
__device__ __nv_bfloat16 g_wih[DIP * DM];
__device__ __nv_bfloat16 g_wil[DIP * DM];
__device__ __nv_bfloat16 g_woh[DM * DSSM];
__device__ __nv_bfloat16 g_wol[DM * DSSM];
__device__ __nv_bfloat16 g_ynh[B_ * L_ * DSSM];
__device__ __nv_bfloat16 g_ynl[B_ * L_ * DSSM];

// ---------------- warp-level MMA helpers (arch-neutral PTX) ----------------
__device__ __forceinline__ uint32_t smem_u32(const void* p) {
    uint32_t a;
    asm("{ .reg .u64 t; cvta.to.shared.u64 t, %1; cvt.u32.u64 %0, t; }" : "=r"(a) : "l"(p));
    return a;
}
__device__ __forceinline__ void ldm4(uint32_t* r, uint32_t addr) {
    asm volatile("ldmatrix.sync.aligned.m8n8.x4.shared.b16 {%0,%1,%2,%3}, [%4];"
                 : "=r"(r[0]), "=r"(r[1]), "=r"(r[2]), "=r"(r[3]) : "r"(addr));
}
__device__ __forceinline__ void mma16816(float* d, const uint32_t* a,
                                         uint32_t b0, uint32_t b1) {
    asm volatile(
        "mma.sync.aligned.m16n8k16.row.col.f32.bf16.bf16.f32 "
        "{%0,%1,%2,%3}, {%4,%5,%6,%7}, {%8,%9}, {%0,%1,%2,%3};"
        : "+f"(d[0]), "+f"(d[1]), "+f"(d[2]), "+f"(d[3])
        : "r"(a[0]), "r"(a[1]), "r"(a[2]), "r"(a[3]), "r"(b0), "r"(b1));
}
__device__ __forceinline__ void cpasync16(uint32_t dst, const void* src, int sz) {
    asm volatile("cp.async.cg.shared.global [%0], [%1], 16, %2;"
                 :: "r"(dst), "l"(src), "r"(sz) : "memory");
}
#define CP_COMMIT() asm volatile("cp.async.commit_group;" ::: "memory")
#define CP_WAIT0()  asm volatile("cp.async.wait_group 0;" ::: "memory")
#define CP_WAIT1()  asm volatile("cp.async.wait_group 1;" ::: "memory")

// chunk swizzle for 64-byte rows: conflict-free 8-row ldmatrix gathers
#define CSWZ(r, c) ((((c) ^ (((r) >> 1) & 3))) << 4)

// pack two fp32 into bf16x2 hi word + bf16x2 lo-correction word
__device__ __forceinline__ void split2(float a, float b, uint32_t& hi, uint32_t& lo) {
    __nv_bfloat16 ha = __float2bfloat16(a), hb = __float2bfloat16(b);
    __nv_bfloat16 la = __float2bfloat16(a - __bfloat162float(ha));
    __nv_bfloat16 lb = __float2bfloat16(b - __bfloat162float(hb));
    __nv_bfloat162 H{ha, hb}, L{la, lb};
    hi = *(uint32_t*)&H;
    lo = *(uint32_t*)&L;
}

// ---------------- fp32 -> bf16 hi/lo split ----------------
__global__ __launch_bounds__(256) void split_bf16(const float* __restrict__ src,
                                                  __nv_bfloat16* __restrict__ hi,
                                                  __nv_bfloat16* __restrict__ lo,
                                                  int n4) {
    int i = blockIdx.x * 256 + threadIdx.x;
    if (i >= n4) return;
    float4 v = ((const float4*)src)[i];
    uint32_t h0, l0, h1, l1;
    split2(v.x, v.y, h0, l0);
    split2(v.z, v.w, h1, l1);
    ((uint32_t*)hi)[2 * i + 0] = h0;
    ((uint32_t*)hi)[2 * i + 1] = h1;
    ((uint32_t*)lo)[2 * i + 0] = l0;
    ((uint32_t*)lo)[2 * i + 1] = l1;
}

// ---------------- split-bf16 HMMA GEMM: C[M,N] = A[M,K] @ B[N,K]^T --------
#define GM_SMEM 65536

__global__ __launch_bounds__(256, 2) void gemm_mma(const __nv_bfloat16* __restrict__ Ah,
                                                   const __nv_bfloat16* __restrict__ Al,
                                                   const __nv_bfloat16* __restrict__ Bh,
                                                   const __nv_bfloat16* __restrict__ Bl,
                                                   float* __restrict__ C,
                                                   int M, int N, int K) {
    extern __shared__ __align__(1024) char sm[];
    const int tid = threadIdx.x;
    const int m0 = blockIdx.y * 128, n0 = blockIdx.x * 128;
    const uint32_t sb0 = smem_u32(sm);
    const int warp = tid >> 5, lane = tid & 31;
    const int warp_m = warp & 3, warp_n = warp >> 2;
    const int KT = K >> 5;

    float acc[2][8][4];
#pragma unroll
    for (int a = 0; a < 2; a++)
#pragma unroll
        for (int b = 0; b < 8; b++)
#pragma unroll
            for (int c = 0; c < 4; c++) acc[a][b][c] = 0.f;

    auto load_stage = [&](int kt, int s) {
        const uint32_t sb = sb0 + s * 32768;
        const int k0 = kt << 5;
#pragma unroll
        for (int ii = 0; ii < 2; ii++) {
            const int i = tid + ii * 256;
            const int r = i >> 2, c = i & 3;
            const uint32_t sw = (uint32_t)(r * 64) + CSWZ(r, c);
            const size_t ga = (size_t)(m0 + r) * K + k0 + c * 8;
            cpasync16(sb + sw, Ah + ga, 16);
            cpasync16(sb + 8192 + sw, Al + ga, 16);
            const int rb = (n0 + r < N) ? (n0 + r) : (N - 1);
            const int bs = (n0 + r < N) ? 16 : 0;
            const size_t gb = (size_t)rb * K + k0 + c * 8;
            cpasync16(sb + 16384 + sw, Bh + gb, bs);
            cpasync16(sb + 24576 + sw, Bl + gb, bs);
        }
    };

    load_stage(0, 0);
    CP_COMMIT();

    const int lrow = (lane & 7) + ((lane >> 3) & 1) * 8;
    const int lhalf = lane >> 4;

    for (int kt = 0; kt < KT; kt++) {
        if (kt + 1 < KT) {
            load_stage(kt + 1, (kt + 1) & 1);
            CP_COMMIT();
            CP_WAIT1();
        } else {
            CP_WAIT0();
        }
        __syncthreads();

        const uint32_t sb = sb0 + (kt & 1) * 32768;
#pragma unroll
        for (int ki = 0; ki < 2; ki++) {
            const int chunk = ki * 2 + lhalf;
            uint32_t ah[2][4], al[2][4];
#pragma unroll
            for (int mi = 0; mi < 2; mi++) {
                const int r = warp_m * 32 + mi * 16 + lrow;
                const uint32_t off = (uint32_t)(r * 64) + CSWZ(r, chunk);
                ldm4(ah[mi], sb + off);
                ldm4(al[mi], sb + 8192 + off);
            }
            uint32_t bh[4][4], bl[4][4];
#pragma unroll
            for (int nj = 0; nj < 4; nj++) {
                const int r = warp_n * 64 + nj * 16 + lrow;
                const uint32_t off = (uint32_t)(r * 64) + CSWZ(r, chunk);
                ldm4(bh[nj], sb + 16384 + off);
                ldm4(bl[nj], sb + 24576 + off);
            }
#pragma unroll
            for (int mi = 0; mi < 2; mi++)
#pragma unroll
                for (int nj = 0; nj < 8; nj++) {
                    const int g = nj >> 1, h = nj & 1;
                    mma16816(acc[mi][nj], ah[mi], bh[g][h], bh[g][h + 2]);
                    mma16816(acc[mi][nj], ah[mi], bl[g][h], bl[g][h + 2]);
                    mma16816(acc[mi][nj], al[mi], bh[g][h], bh[g][h + 2]);
                }
        }
        __syncthreads();
    }

#pragma unroll
    for (int mi = 0; mi < 2; mi++)
#pragma unroll
        for (int nj = 0; nj < 8; nj++) {
            const int row = m0 + warp_m * 32 + mi * 16 + (lane >> 2);
            const int col = n0 + warp_n * 64 + nj * 8 + (lane & 3) * 2;
            if (col < N) {
                float2 v0 = make_float2(acc[mi][nj][0], acc[mi][nj][1]);
                float2 v1 = make_float2(acc[mi][nj][2], acc[mi][nj][3]);
                *(float2*)&C[(size_t)row * N + col] = v0;
                *(float2*)&C[(size_t)(row + 8) * N + col] = v1;
            }
        }
}

// ---------------- tree conv + silu + dt softplus ----------------
__global__ __launch_bounds__(256) void kernel_conv(const int* __restrict__ cidx,
                                                   const float* __restrict__ cw,
                                                   const float* __restrict__ cb,
                                                   const float* __restrict__ dtb) {
    const int bt = blockIdx.x;           // b*L_ + t
    const int b = bt / L_, t = bt - b * L_;
    const int tid = threadIdx.x;

    __shared__ int idx[4];
    if (tid < 4) idx[tid] = cidx[(size_t)b * 4 * L_ + 4 * t + tid];
    __syncthreads();
    const int i0 = idx[0], i1 = idx[1], i2 = idx[2], i3 = idx[3];

    for (int c = tid; c < CD; c += 256) {
        float acc = cb[c];
        const float* w = cw + c * 4;
        if (i0) acc += g_zx[(size_t)(b * L_ + i0 - 1) * DIP + DSSM + c] * w[0];
        if (i1) acc += g_zx[(size_t)(b * L_ + i1 - 1) * DIP + DSSM + c] * w[1];
        if (i2) acc += g_zx[(size_t)(b * L_ + i2 - 1) * DIP + DSSM + c] * w[2];
        if (i3) acc += g_zx[(size_t)(b * L_ + i3 - 1) * DIP + DSSM + c] * w[3];
        g_xBC[(size_t)bt * CD + c] = acc / (1.f + __expf(-acc));   // silu
    }
    if (tid < NH) {
        float x = g_zx[(size_t)bt * DIP + DSSM + CD + tid] + dtb[tid];
        g_dt[bt * NH + tid] = (x > 20.f) ? x : log1pf(expf(x));    // softplus
    }
}

// ---------------- per-(b,c,h) inclusive cumsum of dt*A ----------------
__global__ __launch_bounds__(256) void kernel_cumA(const float* __restrict__ A_log) {
    const int blk = blockIdx.x;                 // (b*NC+c)*NH + h
    const int h = blk & (NH - 1);
    const int bc = blk / NH;
    const int b = bc / NC, c = bc - b * NC;
    const int t = threadIdx.x;
    const float Ah = -expf(A_log[h]);
    const int l = b * L_ + c * CH + t;
    __shared__ float s[CH];
    s[t] = g_dt[l * NH + h] * Ah;
    __syncthreads();
    for (int off = 1; off < CH; off <<= 1) {
        float add = (t >= off) ? s[t - off] : 0.f;
        __syncthreads();
        s[t] += add;
        __syncthreads();
    }
    g_cumA[blk * CH + t] = s[t];
}

// ---------------- G = C @ B^T per (b,chunk): 256x256, K=128 --------------
__global__ void kernel_G() {
    const int bc = blockIdx.z;                 // b*NC + c
    const int t0 = blockIdx.y * 16, s0 = blockIdx.x * 16;
    const int tx = threadIdx.x, ty = threadIdx.y;
    const int tid = ty * 16 + tx;
    __shared__ float Cs[16][129];
    __shared__ float Bs[16][129];
    const int b = bc / NC, c = bc - b * NC;
    const int base_l = b * L_ + c * CH;
    for (int i = tid; i < 16 * 128; i += 256) {
        int row = i >> 7, n = i & 127;
        Cs[row][n] = g_xBC[(size_t)(base_l + t0 + row) * CD + DSSM + DS + n];
        Bs[row][n] = g_xBC[(size_t)(base_l + s0 + row) * CD + DSSM + n];
    }
    __syncthreads();
    float acc = 0.f;
#pragma unroll 8
    for (int n = 0; n < 128; n++) acc += Cs[ty][n] * Bs[tx][n];
    g_G[((size_t)bc * CH + t0 + ty) * CH + s0 + tx] = acc;
}

// ---------------- states on HMMA: S[p,n] = sum_s ws[s]*x[s,p]*B[s,n] -----
// M=64 (p), N=128 (n), K=256 (s). Warp grid 2m x 4n.
#define ST_CUMA 0
#define ST_WS   1024
#define ST_A    2048
#define ST_ALO  6144
#define ST_B    10240
#define ST_BLO  18432
#define ST_BSTG 26624                    // [32][129] fp32 = 16512 B
#define ST_XSTG 43136                    // [32][65]  fp32 = 8320 B
#define ST_SMEM 51456

__global__ __launch_bounds__(256) void kernel_states_mma() {
    extern __shared__ __align__(1024) char sm[];
    const int blk = blockIdx.x;
    const int h = blk & (NH - 1);
    const int bc = blk / NH;
    const int b = bc / NC, c = bc - b * NC;
    const int tid = threadIdx.x;
    const int base_l = b * L_ + c * CH;
    const uint32_t sb = smem_u32(sm);
    float* cumA_sh = (float*)(sm + ST_CUMA);
    float* ws_sh = (float*)(sm + ST_WS);
    float* Bstg = (float*)(sm + ST_BSTG);
    float* xstg = (float*)(sm + ST_XSTG);

    cumA_sh[tid] = g_cumA[blk * CH + tid];
    __syncthreads();
    ws_sh[tid] = g_dt[(base_l + tid) * NH + h] * __expf(cumA_sh[CH - 1] - cumA_sh[tid]);
    __syncthreads();

    const int warp = tid >> 5, lane = tid & 31;
    const int warp_m = warp & 1, warp_n = warp >> 1;
    const int lrow = (lane & 7) + ((lane >> 3) & 1) * 8;
    const int lhalf = lane >> 4;

    float acc[2][4][4];
#pragma unroll
    for (int a = 0; a < 2; a++)
#pragma unroll
        for (int bq = 0; bq < 4; bq++)
#pragma unroll
            for (int cq = 0; cq < 4; cq++) acc[a][bq][cq] = 0.f;

    for (int s0 = 0; s0 < CH; s0 += 32) {
        // stage B chunk [32 s][128 n] and x chunk [32 s][64 p], coalesced
#pragma unroll
        for (int ii = 0; ii < 16; ii++) {
            const int i = tid + ii * 256;
            const int s = i >> 7, n = i & 127;
            Bstg[s * 129 + n] = g_xBC[(size_t)(base_l + s0 + s) * CD + DSSM + n];
        }
#pragma unroll
        for (int ii = 0; ii < 8; ii++) {
            const int i = tid + ii * 256;
            const int s = i >> 6, p = i & 63;
            xstg[s * 65 + p] = g_xBC[(size_t)(base_l + s0 + s) * CD + h * HD + p];
        }
        __syncthreads();
        // build Bt[n][s] operand (hi/lo), pairs over s
#pragma unroll
        for (int jj = 0; jj < 8; jj++) {
            const int j = tid + jj * 256;              // 2048
            const int n = j >> 4, sl = (j & 15) * 2;
            uint32_t hi, lo;
            split2(Bstg[sl * 129 + n], Bstg[(sl + 1) * 129 + n], hi, lo);
            const uint32_t a = (uint32_t)(n * 64) + CSWZ(n, sl >> 3) + (sl & 7) * 2;
            *(uint32_t*)(sm + ST_B + a) = hi;
            *(uint32_t*)(sm + ST_BLO + a) = lo;
        }
        // build A[p][s] = x[s,p]*ws[s]
#pragma unroll
        for (int jj = 0; jj < 4; jj++) {
            const int j = tid + jj * 256;              // 1024
            const int p = j >> 4, sl = (j & 15) * 2;
            uint32_t hi, lo;
            split2(xstg[sl * 65 + p] * ws_sh[s0 + sl],
                   xstg[(sl + 1) * 65 + p] * ws_sh[s0 + sl + 1], hi, lo);
            const uint32_t a = (uint32_t)(p * 64) + CSWZ(p, sl >> 3) + (sl & 7) * 2;
            *(uint32_t*)(sm + ST_A + a) = hi;
            *(uint32_t*)(sm + ST_ALO + a) = lo;
        }
        __syncthreads();
#pragma unroll
        for (int ki = 0; ki < 2; ki++) {
            const int chunk = ki * 2 + lhalf;
            uint32_t ah[2][4], al[2][4];
#pragma unroll
            for (int mi = 0; mi < 2; mi++) {
                const int r = warp_m * 32 + mi * 16 + lrow;
                const uint32_t off = (uint32_t)(r * 64) + CSWZ(r, chunk);
                ldm4(ah[mi], sb + ST_A + off);
                ldm4(al[mi], sb + ST_ALO + off);
            }
            uint32_t bh[2][4], bl[2][4];
#pragma unroll
            for (int nj = 0; nj < 2; nj++) {
                const int r = warp_n * 32 + nj * 16 + lrow;
                const uint32_t off = (uint32_t)(r * 64) + CSWZ(r, chunk);
                ldm4(bh[nj], sb + ST_B + off);
                ldm4(bl[nj], sb + ST_BLO + off);
            }
#pragma unroll
            for (int mi = 0; mi < 2; mi++)
#pragma unroll
                for (int nj = 0; nj < 4; nj++) {
                    const int g = nj >> 1, hh = nj & 1;
                    mma16816(acc[mi][nj], ah[mi], bh[g][hh], bh[g][hh + 2]);
                    mma16816(acc[mi][nj], ah[mi], bl[g][hh], bl[g][hh + 2]);
                    mma16816(acc[mi][nj], al[mi], bh[g][hh], bh[g][hh + 2]);
                }
        }
        __syncthreads();
    }

#pragma unroll
    for (int mi = 0; mi < 2; mi++)
#pragma unroll
        for (int nj = 0; nj < 4; nj++) {
            const int row = warp_m * 32 + mi * 16 + (lane >> 2);
            const int col = warp_n * 32 + nj * 8 + (lane & 3) * 2;
            float* dst = &g_states[(size_t)blk * HD * DS + (size_t)row * DS + col];
            *(float2*)dst = make_float2(acc[mi][nj][0], acc[mi][nj][1]);
            *(float2*)(dst + 8 * DS) = make_float2(acc[mi][nj][2], acc[mi][nj][3]);
        }
}

// ---------------- inter-chunk recurrence (sequential over chunks) --------
__global__ __launch_bounds__(256) void kernel_scan() {
    const int b = blockIdx.x >> 5;
    const int h = blockIdx.x & 31;
    const int tid = threadIdx.x;
    float4 prev[8];
#pragma unroll
    for (int i = 0; i < 8; i++) prev[i] = make_float4(0.f, 0.f, 0.f, 0.f);
    for (int c = 0; c < NC; c++) {
        int blk = (b * NC + c) * NH + h;
        float cd = __expf(g_cumA[blk * CH + CH - 1]);
        const float4* st = (const float4*)&g_states[(size_t)blk * HD * DS];
        float4* pv = (float4*)&g_prev[(size_t)blk * HD * DS];
#pragma unroll
        for (int i = 0; i < 8; i++) {
            float4 s = st[tid + i * 256];
            float4 pr = prev[i];
            pv[tid + i * 256] = pr;
            prev[i] = make_float4(pr.x * cd + s.x, pr.y * cd + s.y,
                                  pr.z * cd + s.z, pr.w * cd + s.w);
        }
    }
}

// ---------------- fused Yd + Yoff + D*x on HMMA --------------------------
// Y[t,p] = sum_s (G[t,s]*L[t,s]*dt[s]) x[s,p]  +  eA[t]*sum_n C[t,n]*prev[p,n]
//          + D[h]*x[t,p].   M=256 (t), N=64 (p). Warp grid 8m x 1n.
#define YO_CUMA  0
#define YO_DT    1024
#define YO_EA    2048
#define YO_W     3072                    // 16KB [256][64B]
#define YO_WLO   19456
#define YO_XT    35840                   // 4KB [64][64B]
#define YO_XTLO  39936
#define YO_STAGE 44032                   // [32][65] fp32 = 8320 B
#define YO_SMEM  52352

__global__ __launch_bounds__(256) void kernel_ydoff_mma(const float* __restrict__ Dv) {
    extern __shared__ __align__(1024) char sm[];
    const int blk = blockIdx.x;
    const int h = blk & (NH - 1);
    const int bc = blk / NH;
    const int b = bc / NC, c = bc - b * NC;
    const int tid = threadIdx.x;
    const int base_l = b * L_ + c * CH;
    const uint32_t sb = smem_u32(sm);
    float* cumA_sh = (float*)(sm + YO_CUMA);
    float* dt_sh = (float*)(sm + YO_DT);
    float* eA_sh = (float*)(sm + YO_EA);
    float* stg = (float*)(sm + YO_STAGE);
    const float* Gb = g_G + (size_t)bc * CH * CH;

    cumA_sh[tid] = g_cumA[blk * CH + tid];
    dt_sh[tid] = g_dt[(base_l + tid) * NH + h];
    __syncthreads();
    eA_sh[tid] = __expf(cumA_sh[tid]);
    __syncthreads();

    const int warp = tid >> 5, lane = tid & 31;
    const int lrow = (lane & 7) + ((lane >> 3) & 1) * 8;
    const int lhalf = lane >> 4;

    float acc[2][8][4];
#pragma unroll
    for (int a = 0; a < 2; a++)
#pragma unroll
        for (int bq = 0; bq < 8; bq++)
#pragma unroll
            for (int cq = 0; cq < 4; cq++) acc[a][bq][cq] = 0.f;

    // ---- phase 1: Yd over s-chunks ----
    for (int s0 = 0; s0 < CH; s0 += 32) {
#pragma unroll
        for (int ii = 0; ii < 8; ii++) {
            const int i = tid + ii * 256;
            const int s = i >> 6, p = i & 63;
            stg[s * 65 + p] = g_xBC[(size_t)(base_l + s0 + s) * CD + h * HD + p];
        }
        __syncthreads();
        // W[t][sl] = mask * G * exp(cumA[t]-cumA[s]) * dt[s]
#pragma unroll
        for (int jj = 0; jj < 16; jj++) {
            const int j = tid + jj * 256;              // 4096
            const int t = j >> 4, sl = (j & 15) * 2;
            const int sg = s0 + sl;
            const float cat = cumA_sh[t];
            float w0 = (t >= sg) ? Gb[t * CH + sg] * __expf(cat - cumA_sh[sg]) * dt_sh[sg] : 0.f;
            float w1 = (t >= sg + 1) ? Gb[t * CH + sg + 1] * __expf(cat - cumA_sh[sg + 1]) * dt_sh[sg + 1] : 0.f;
            uint32_t hi, lo;
            split2(w0, w1, hi, lo);
            const uint32_t a = (uint32_t)(t * 64) + CSWZ(t, sl >> 3) + (sl & 7) * 2;
            *(uint32_t*)(sm + YO_W + a) = hi;
            *(uint32_t*)(sm + YO_WLO + a) = lo;
        }
        // xT[p][sl]
#pragma unroll
        for (int jj = 0; jj < 4; jj++) {
            const int j = tid + jj * 256;              // 1024
            const int p = j >> 4, sl = (j & 15) * 2;
            uint32_t hi, lo;
            split2(stg[sl * 65 + p], stg[(sl + 1) * 65 + p], hi, lo);
            const uint32_t a = (uint32_t)(p * 64) + CSWZ(p, sl >> 3) + (sl & 7) * 2;
            *(uint32_t*)(sm + YO_XT + a) = hi;
            *(uint32_t*)(sm + YO_XTLO + a) = lo;
        }
        __syncthreads();
#pragma unroll
        for (int ki = 0; ki < 2; ki++) {
            const int chunk = ki * 2 + lhalf;
            uint32_t ah[2][4], al[2][4];
#pragma unroll
            for (int mi = 0; mi < 2; mi++) {
                const int r = warp * 32 + mi * 16 + lrow;
                const uint32_t off = (uint32_t)(r * 64) + CSWZ(r, chunk);
                ldm4(ah[mi], sb + YO_W + off);
                ldm4(al[mi], sb + YO_WLO + off);
            }
            uint32_t bh[4][4], bl[4][4];
#pragma unroll
            for (int nj = 0; nj < 4; nj++) {
                const int r = nj * 16 + lrow;
                const uint32_t off = (uint32_t)(r * 64) + CSWZ(r, chunk);
                ldm4(bh[nj], sb + YO_XT + off);
                ldm4(bl[nj], sb + YO_XTLO + off);
            }
#pragma unroll
            for (int mi = 0; mi < 2; mi++)
#pragma unroll
                for (int nj = 0; nj < 8; nj++) {
                    const int g = nj >> 1, hh = nj & 1;
                    mma16816(acc[mi][nj], ah[mi], bh[g][hh], bh[g][hh + 2]);
                    mma16816(acc[mi][nj], ah[mi], bl[g][hh], bl[g][hh + 2]);
                    mma16816(acc[mi][nj], al[mi], bh[g][hh], bh[g][hh + 2]);
                }
        }
        __syncthreads();
    }

    // ---- phase 2: Yoff over n-chunks ----
    const float* prev_base = &g_prev[(size_t)blk * HD * DS];
    for (int n0 = 0; n0 < DS; n0 += 32) {
        // Ct[t][nl] = C[t,n]*eA[t]
#pragma unroll
        for (int jj = 0; jj < 16; jj++) {
            const int j = tid + jj * 256;              // 4096
            const int t = j >> 4, nl = (j & 15) * 2;
            const float ea = eA_sh[t];
            const float* cp = &g_xBC[(size_t)(base_l + t) * CD + DSSM + DS + n0 + nl];
            uint32_t hi, lo;
            split2(cp[0] * ea, cp[1] * ea, hi, lo);
            const uint32_t a = (uint32_t)(t * 64) + CSWZ(t, nl >> 3) + (nl & 7) * 2;
            *(uint32_t*)(sm + YO_W + a) = hi;
            *(uint32_t*)(sm + YO_WLO + a) = lo;
        }
        // prev[p][nl]  (already [p][n] row-major)
#pragma unroll
        for (int jj = 0; jj < 4; jj++) {
            const int j = tid + jj * 256;              // 1024
            const int p = j >> 4, nl = (j & 15) * 2;
            const float* pp = &prev_base[(size_t)p * DS + n0 + nl];
            uint32_t hi, lo;
            split2(pp[0], pp[1], hi, lo);
            const uint32_t a = (uint32_t)(p * 64) + CSWZ(p, nl >> 3) + (nl & 7) * 2;
            *(uint32_t*)(sm + YO_XT + a) = hi;
            *(uint32_t*)(sm + YO_XTLO + a) = lo;
        }
        __syncthreads();
#pragma unroll
        for (int ki = 0; ki < 2; ki++) {
            const int chunk = ki * 2 + lhalf;
            uint32_t ah[2][4], al[2][4];
#pragma unroll
            for (int mi = 0; mi < 2; mi++) {
                const int r = warp * 32 + mi * 16 + lrow;
                const uint32_t off = (uint32_t)(r * 64) + CSWZ(r, chunk);
                ldm4(ah[mi], sb + YO_W + off);
                ldm4(al[mi], sb + YO_WLO + off);
            }
            uint32_t bh[4][4], bl[4][4];
#pragma unroll
            for (int nj = 0; nj < 4; nj++) {
                const int r = nj * 16 + lrow;
                const uint32_t off = (uint32_t)(r * 64) + CSWZ(r, chunk);
                ldm4(bh[nj], sb + YO_XT + off);
                ldm4(bl[nj], sb + YO_XTLO + off);
            }
#pragma unroll
            for (int mi = 0; mi < 2; mi++)
#pragma unroll
                for (int nj = 0; nj < 8; nj++) {
                    const int g = nj >> 1, hh = nj & 1;
                    mma16816(acc[mi][nj], ah[mi], bh[g][hh], bh[g][hh + 2]);
                    mma16816(acc[mi][nj], ah[mi], bl[g][hh], bl[g][hh + 2]);
                    mma16816(acc[mi][nj], al[mi], bh[g][hh], bh[g][hh + 2]);
                }
        }
        __syncthreads();
    }

    // ---- epilogue: + D[h]*x, write Y ----
    const float Dh = Dv[h];
#pragma unroll
    for (int mi = 0; mi < 2; mi++)
#pragma unroll
        for (int nj = 0; nj < 8; nj++) {
            const int row = warp * 32 + mi * 16 + (lane >> 2);
            const int col = nj * 8 + (lane & 3) * 2;
            const size_t l0 = (size_t)(base_l + row);
            float2 x0 = *(const float2*)&g_xBC[l0 * CD + h * HD + col];
            float2 x1 = *(const float2*)&g_xBC[(l0 + 8) * CD + h * HD + col];
            *(float2*)&g_Y[l0 * DSSM + h * HD + col] =
                make_float2(acc[mi][nj][0] + Dh * x0.x, acc[mi][nj][1] + Dh * x0.y);
            *(float2*)&g_Y[(l0 + 8) * DSSM + h * HD + col] =
                make_float2(acc[mi][nj][2] + Dh * x1.x, acc[mi][nj][3] + Dh * x1.y);
        }
}

// ---------------- gated RMSNorm -> bf16 hi/lo ----------------
__global__ __launch_bounds__(256) void kernel_norm(const float* __restrict__ nw) {
    const int row = blockIdx.x;
    const int tid = threadIdx.x;
    const float* y = &g_Y[(size_t)row * DSSM];
    const float* z = &g_zx[(size_t)row * DIP];  // z = first DSSM cols
    float v[8];
    float sum = 0.f;
#pragma unroll
    for (int i = 0; i < 8; i++) {
        int cc = tid + i * 256;
        float zz = z[cc];
        float vv = y[cc] * (zz / (1.f + __expf(-zz)));
        v[i] = vv;
        sum += vv * vv;
    }
    __shared__ float red[256];
    red[tid] = sum;
    __syncthreads();
    for (int off = 128; off; off >>= 1) {
        if (tid < off) red[tid] += red[tid + off];
        __syncthreads();
    }
    const float scale = rsqrtf(red[0] * (1.f / DSSM) + 1e-5f);
#pragma unroll
    for (int i = 0; i < 8; i++) {
        int cc = tid + i * 256;
        float o = v[i] * scale * nw[cc];
        __nv_bfloat16 h = __float2bfloat16(o);
        g_ynh[(size_t)row * DSSM + cc] = h;
        g_ynl[(size_t)row * DSSM + cc] = __float2bfloat16(o - __bfloat162float(h));
    }
}

// ---------------- launch ----------------
extern "C" void kernel_launch(void* const* d_in, const int* in_sizes, int n_in,
                              void* d_out, int out_size) {
    const float* u     = (const float*)d_in[0];
    const int*   cidx  = (const int*)d_in[1];
    const float* W_in  = (const float*)d_in[2];
    const float* cw    = (const float*)d_in[3];
    const float* cb    = (const float*)d_in[4];
    const float* dtb   = (const float*)d_in[5];
    const float* A_log = (const float*)d_in[6];
    const float* Dv    = (const float*)d_in[7];
    const float* nw    = (const float*)d_in[8];
    const float* W_out = (const float*)d_in[9];
    float* out = (float*)d_out;

    float* zx_p;
    __nv_bfloat16 *uh, *ul, *wih, *wil, *woh, *wol, *ynh, *ynl;
    cudaGetSymbolAddress((void**)&zx_p, g_zx);
    cudaGetSymbolAddress((void**)&uh, g_uh);
    cudaGetSymbolAddress((void**)&ul, g_ul);
    cudaGetSymbolAddress((void**)&wih, g_wih);
    cudaGetSymbolAddress((void**)&wil, g_wil);
    cudaGetSymbolAddress((void**)&woh, g_woh);
    cudaGetSymbolAddress((void**)&wol, g_wol);
    cudaGetSymbolAddress((void**)&ynh, g_ynh);
    cudaGetSymbolAddress((void**)&ynl, g_ynl);

    cudaFuncSetAttribute(gemm_mma, cudaFuncAttributeMaxDynamicSharedMemorySize, GM_SMEM);
    cudaFuncSetAttribute(kernel_states_mma, cudaFuncAttributeMaxDynamicSharedMemorySize, ST_SMEM);
    cudaFuncSetAttribute(kernel_ydoff_mma, cudaFuncAttributeMaxDynamicSharedMemorySize, YO_SMEM);

    // 0) split fp32 -> bf16 hi/lo
    {
        int n4;
        n4 = (B_ * L_ * DM) / 4;
        split_bf16<<<(n4 + 255) / 256, 256>>>(u, uh, ul, n4);
        n4 = (DIP * DM) / 4;
        split_bf16<<<(n4 + 255) / 256, 256>>>(W_in, wih, wil, n4);
        n4 = (DM * DSSM) / 4;
        split_bf16<<<(n4 + 255) / 256, 256>>>(W_out, woh, wol, n4);
    }
    // 1) zxbcdt = u @ W_in^T   (M=4096, N=4384, K=1024) on HMMA
    gemm_mma<<<dim3((DIP + 127) / 128, (B_ * L_) / 128), 256, GM_SMEM>>>(
        uh, ul, wih, wil, zx_p, B_ * L_, DIP, DM);
    // 2) tree conv + silu + dt softplus
    kernel_conv<<<B_ * L_, 256>>>(cidx, cw, cb, dtb);
    // 3) cumsum(dt*A) per chunk/head
    kernel_cumA<<<B_ * NC * NH, 256>>>(A_log);
    // 4) G = C@B^T per (b,chunk)
    kernel_G<<<dim3(CH / 16, CH / 16, B_ * NC), dim3(16, 16)>>>();
    // 5) chunk end-states on HMMA
    kernel_states_mma<<<B_ * NC * NH, 256, ST_SMEM>>>();
    // 6) inter-chunk scan
    kernel_scan<<<B_ * NH, 256>>>();
    // 7) fused Yd + Yoff + D*x on HMMA
    kernel_ydoff_mma<<<B_ * NC * NH, 256, YO_SMEM>>>(Dv);
    // 8) gated RMSNorm -> bf16 hi/lo
    kernel_norm<<<B_ * L_, 256>>>(nw);
    // 9) out = yn @ W_out^T  (M=4096, N=1024, K=2048) on HMMA
    gemm_mma<<<dim3(DM / 128, (B_ * L_) / 128), 256, GM_SMEM>>>(
        ynh, ynl, woh, wol, out, B_ * L_, DM, DSSM);
}

// round 5
// speedup vs baseline: 3.4850x; 1.4688x over previous
#include <cuda_runtime.h>
#include <cuda_bf16.h>
#include <math.h>
#include <stdint.h>

#define B_   2
#define L_   2048
#define DM   1024
#define DIP  4384
#define DSSM 2048
#define CD   2304
#define NH   32
#define HD   64
#define DS   128
#define CH   256
#define NC   8

// ---------------- scratch (device globals; no allocation) ----------------
__device__ float g_zx[B_ * L_ * DIP];          // in-proj output (z | xBC | dt_raw)
__device__ float g_xBC[B_ * L_ * CD];          // post-conv+silu (x | B | C)
__device__ float g_dt[B_ * L_ * NH];           // softplus dt
__device__ float g_G[B_ * NC * CH * CH];       // per-chunk C@B^T (head-independent)
__device__ float g_cumA[B_ * NC * NH * CH];    // inclusive cumsum of dt*A per chunk
__device__ float g_states[B_ * NC * NH * HD * DS];
__device__ float g_prev[B_ * NC * NH * HD * DS];
__device__ float g_Y[B_ * L_ * DSSM];

// bf16 split-precision operand buffers for tensor-core GEMMs
__device__ __nv_bfloat16 g_uh[B_ * L_ * DM];
__device__ __nv_bfloat16 g_ul[B_ * L_ * DM];
__device__ __nv_bfloat16 g_wih[DIP * DM];
__device__ __nv_bfloat16 g_wil[DIP * DM];
__device__ __nv_bfloat16 g_woh[DM * DSSM];
__device__ __nv_bfloat16 g_wol[DM * DSSM];
__device__ __nv_bfloat16 g_ynh[B_ * L_ * DSSM];
__device__ __nv_bfloat16 g_ynl[B_ * L_ * DSSM];

// ---------------- warp-level MMA helpers (arch-neutral PTX) ----------------
__device__ __forceinline__ uint32_t smem_u32(const void* p) {
    uint32_t a;
    asm("{ .reg .u64 t; cvta.to.shared.u64 t, %1; cvt.u32.u64 %0, t; }" : "=r"(a) : "l"(p));
    return a;
}
__device__ __forceinline__ void ldm4(uint32_t* r, uint32_t addr) {
    asm volatile("ldmatrix.sync.aligned.m8n8.x4.shared.b16 {%0,%1,%2,%3}, [%4];"
                 : "=r"(r[0]), "=r"(r[1]), "=r"(r[2]), "=r"(r[3]) : "r"(addr));
}
__device__ __forceinline__ void mma16816(float* d, const uint32_t* a,
                                         uint32_t b0, uint32_t b1) {
    asm volatile(
        "mma.sync.aligned.m16n8k16.row.col.f32.bf16.bf16.f32 "
        "{%0,%1,%2,%3}, {%4,%5,%6,%7}, {%8,%9}, {%0,%1,%2,%3};"
        : "+f"(d[0]), "+f"(d[1]), "+f"(d[2]), "+f"(d[3])
        : "r"(a[0]), "r"(a[1]), "r"(a[2]), "r"(a[3]), "r"(b0), "r"(b1));
}
__device__ __forceinline__ void cpasync16(uint32_t dst, const void* src, int sz) {
    asm volatile("cp.async.cg.shared.global [%0], [%1], 16, %2;"
                 :: "r"(dst), "l"(src), "r"(sz) : "memory");
}
#define CP_COMMIT() asm volatile("cp.async.commit_group;" ::: "memory")
#define CP_WAIT0()  asm volatile("cp.async.wait_group 0;" ::: "memory")
#define CP_WAIT1()  asm volatile("cp.async.wait_group 1;" ::: "memory")

// chunk swizzle for 64-byte rows: conflict-free 8-row ldmatrix gathers
#define CSWZ(r, c) ((((c) ^ (((r) >> 1) & 3))) << 4)

// pack two fp32 into bf16x2 hi word + bf16x2 lo-correction word
__device__ __forceinline__ void split2(float a, float b, uint32_t& hi, uint32_t& lo) {
    __nv_bfloat16 ha = __float2bfloat16(a), hb = __float2bfloat16(b);
    __nv_bfloat16 la = __float2bfloat16(a - __bfloat162float(ha));
    __nv_bfloat16 lb = __float2bfloat16(b - __bfloat162float(hb));
    __nv_bfloat162 H{ha, hb}, L{la, lb};
    hi = *(uint32_t*)&H;
    lo = *(uint32_t*)&L;
}

// ---------------- fp32 -> bf16 hi/lo split ----------------
__global__ __launch_bounds__(256) void split_bf16(const float* __restrict__ src,
                                                  __nv_bfloat16* __restrict__ hi,
                                                  __nv_bfloat16* __restrict__ lo,
                                                  int n4) {
    int i = blockIdx.x * 256 + threadIdx.x;
    if (i >= n4) return;
    float4 v = ((const float4*)src)[i];
    uint32_t h0, l0, h1, l1;
    split2(v.x, v.y, h0, l0);
    split2(v.z, v.w, h1, l1);
    ((uint32_t*)hi)[2 * i + 0] = h0;
    ((uint32_t*)hi)[2 * i + 1] = h1;
    ((uint32_t*)lo)[2 * i + 0] = l0;
    ((uint32_t*)lo)[2 * i + 1] = l1;
}

// ---------------- split-bf16 HMMA GEMM: C[M,N] = A[M,K] @ B[N,K]^T --------
// 3-stage cp.async pipeline, one __syncthreads per k-tile.
#define GM_SMEM (3 * 32768)

__global__ __launch_bounds__(256, 2) void gemm_mma(const __nv_bfloat16* __restrict__ Ah,
                                                   const __nv_bfloat16* __restrict__ Al,
                                                   const __nv_bfloat16* __restrict__ Bh,
                                                   const __nv_bfloat16* __restrict__ Bl,
                                                   float* __restrict__ C,
                                                   int M, int N, int K) {
    extern __shared__ __align__(1024) char sm[];
    const int tid = threadIdx.x;
    const int m0 = blockIdx.y * 128, n0 = blockIdx.x * 128;
    const uint32_t sb0 = smem_u32(sm);
    const int warp = tid >> 5, lane = tid & 31;
    const int warp_m = warp & 3, warp_n = warp >> 2;
    const int KT = K >> 5;

    float acc[2][8][4];
#pragma unroll
    for (int a = 0; a < 2; a++)
#pragma unroll
        for (int b = 0; b < 8; b++)
#pragma unroll
            for (int c = 0; c < 4; c++) acc[a][b][c] = 0.f;

    auto load_stage = [&](int kt, int s) {
        const uint32_t sb = sb0 + s * 32768;
        const int k0 = kt << 5;
#pragma unroll
        for (int ii = 0; ii < 2; ii++) {
            const int i = tid + ii * 256;
            const int r = i >> 2, c = i & 3;
            const uint32_t sw = (uint32_t)(r * 64) + CSWZ(r, c);
            const size_t ga = (size_t)(m0 + r) * K + k0 + c * 8;
            cpasync16(sb + sw, Ah + ga, 16);
            cpasync16(sb + 8192 + sw, Al + ga, 16);
            const int rb = (n0 + r < N) ? (n0 + r) : (N - 1);
            const int bs = (n0 + r < N) ? 16 : 0;
            const size_t gb = (size_t)rb * K + k0 + c * 8;
            cpasync16(sb + 16384 + sw, Bh + gb, bs);
            cpasync16(sb + 24576 + sw, Bl + gb, bs);
        }
    };

    load_stage(0, 0);
    CP_COMMIT();
    if (KT > 1) {
        load_stage(1, 1);
        CP_COMMIT();
    }

    const int lrow = (lane & 7) + ((lane >> 3) & 1) * 8;
    const int lhalf = lane >> 4;

    for (int kt = 0; kt < KT; kt++) {
        if (kt + 1 < KT) CP_WAIT1(); else CP_WAIT0();
        __syncthreads();
        if (kt + 2 < KT) {
            load_stage(kt + 2, (kt + 2) % 3);
            CP_COMMIT();
        }

        const uint32_t sb = sb0 + (kt % 3) * 32768;
#pragma unroll
        for (int ki = 0; ki < 2; ki++) {
            const int chunk = ki * 2 + lhalf;
            uint32_t ah[2][4], al[2][4];
#pragma unroll
            for (int mi = 0; mi < 2; mi++) {
                const int r = warp_m * 32 + mi * 16 + lrow;
                const uint32_t off = (uint32_t)(r * 64) + CSWZ(r, chunk);
                ldm4(ah[mi], sb + off);
                ldm4(al[mi], sb + 8192 + off);
            }
            uint32_t bh[4][4], bl[4][4];
#pragma unroll
            for (int nj = 0; nj < 4; nj++) {
                const int r = warp_n * 64 + nj * 16 + lrow;
                const uint32_t off = (uint32_t)(r * 64) + CSWZ(r, chunk);
                ldm4(bh[nj], sb + 16384 + off);
                ldm4(bl[nj], sb + 24576 + off);
            }
#pragma unroll
            for (int mi = 0; mi < 2; mi++)
#pragma unroll
                for (int nj = 0; nj < 8; nj++) {
                    const int g = nj >> 1, h = nj & 1;
                    mma16816(acc[mi][nj], ah[mi], bh[g][h], bh[g][h + 2]);
                    mma16816(acc[mi][nj], ah[mi], bl[g][h], bl[g][h + 2]);
                    mma16816(acc[mi][nj], al[mi], bh[g][h], bh[g][h + 2]);
                }
        }
        // no trailing sync: 3-stage ring => next overwrite of this stage is
        // ordered by the barrier at the top of iteration kt+1.
    }

#pragma unroll
    for (int mi = 0; mi < 2; mi++)
#pragma unroll
        for (int nj = 0; nj < 8; nj++) {
            const int row = m0 + warp_m * 32 + mi * 16 + (lane >> 2);
            const int col = n0 + warp_n * 64 + nj * 8 + (lane & 3) * 2;
            if (col < N) {
                float2 v0 = make_float2(acc[mi][nj][0], acc[mi][nj][1]);
                float2 v1 = make_float2(acc[mi][nj][2], acc[mi][nj][3]);
                *(float2*)&C[(size_t)row * N + col] = v0;
                *(float2*)&C[(size_t)(row + 8) * N + col] = v1;
            }
        }
}

// ---------------- tree conv + silu + dt softplus ----------------
__global__ __launch_bounds__(256) void kernel_conv(const int* __restrict__ cidx,
                                                   const float* __restrict__ cw,
                                                   const float* __restrict__ cb,
                                                   const float* __restrict__ dtb) {
    const int bt = blockIdx.x;           // b*L_ + t
    const int b = bt / L_, t = bt - b * L_;
    const int tid = threadIdx.x;

    __shared__ int idx[4];
    if (tid < 4) idx[tid] = cidx[(size_t)b * 4 * L_ + 4 * t + tid];
    __syncthreads();
    const int i0 = idx[0], i1 = idx[1], i2 = idx[2], i3 = idx[3];

    for (int c = tid; c < CD; c += 256) {
        float acc = cb[c];
        const float* w = cw + c * 4;
        if (i0) acc += g_zx[(size_t)(b * L_ + i0 - 1) * DIP + DSSM + c] * w[0];
        if (i1) acc += g_zx[(size_t)(b * L_ + i1 - 1) * DIP + DSSM + c] * w[1];
        if (i2) acc += g_zx[(size_t)(b * L_ + i2 - 1) * DIP + DSSM + c] * w[2];
        if (i3) acc += g_zx[(size_t)(b * L_ + i3 - 1) * DIP + DSSM + c] * w[3];
        g_xBC[(size_t)bt * CD + c] = acc / (1.f + __expf(-acc));   // silu
    }
    if (tid < NH) {
        float x = g_zx[(size_t)bt * DIP + DSSM + CD + tid] + dtb[tid];
        g_dt[bt * NH + tid] = (x > 20.f) ? x : log1pf(expf(x));    // softplus
    }
}

// ---------------- per-(b,c,h) inclusive cumsum of dt*A ----------------
__global__ __launch_bounds__(256) void kernel_cumA(const float* __restrict__ A_log) {
    const int blk = blockIdx.x;                 // (b*NC+c)*NH + h
    const int h = blk & (NH - 1);
    const int bc = blk / NH;
    const int b = bc / NC, c = bc - b * NC;
    const int t = threadIdx.x;
    const float Ah = -expf(A_log[h]);
    const int l = b * L_ + c * CH + t;
    __shared__ float s[CH];
    s[t] = g_dt[l * NH + h] * Ah;
    __syncthreads();
    for (int off = 1; off < CH; off <<= 1) {
        float add = (t >= off) ? s[t - off] : 0.f;
        __syncthreads();
        s[t] += add;
        __syncthreads();
    }
    g_cumA[blk * CH + t] = s[t];
}

// ---------------- G = C @ B^T per (b,chunk): lower-triangle blocks only --
__global__ void kernel_G() {
    const int bc = blockIdx.z;                 // b*NC + c
    const int t0 = blockIdx.y * 16, s0 = blockIdx.x * 16;
    if (t0 + 16 <= s0) return;                 // upper triangle never read
    const int tx = threadIdx.x, ty = threadIdx.y;
    const int tid = ty * 16 + tx;
    __shared__ float Cs[16][129];
    __shared__ float Bs[16][129];
    const int b = bc / NC, c = bc - b * NC;
    const int base_l = b * L_ + c * CH;
    for (int i = tid; i < 16 * 128; i += 256) {
        int row = i >> 7, n = i & 127;
        Cs[row][n] = g_xBC[(size_t)(base_l + t0 + row) * CD + DSSM + DS + n];
        Bs[row][n] = g_xBC[(size_t)(base_l + s0 + row) * CD + DSSM + n];
    }
    __syncthreads();
    float acc = 0.f;
#pragma unroll 8
    for (int n = 0; n < 128; n++) acc += Cs[ty][n] * Bs[tx][n];
    g_G[((size_t)bc * CH + t0 + ty) * CH + s0 + tx] = acc;
}

// ---------------- states on HMMA: S[p,n] = sum_s ws[s]*x[s,p]*B[s,n] -----
#define ST_CUMA 0
#define ST_WS   1024
#define ST_A    2048
#define ST_ALO  6144
#define ST_B    10240
#define ST_BLO  18432
#define ST_BSTG 26624                    // [32][129] fp32 = 16512 B
#define ST_XSTG 43136                    // [32][65]  fp32 = 8320 B
#define ST_SMEM 51456

__global__ __launch_bounds__(256) void kernel_states_mma() {
    extern __shared__ __align__(1024) char sm[];
    const int blk = blockIdx.x;
    const int h = blk & (NH - 1);
    const int bc = blk / NH;
    const int b = bc / NC, c = bc - b * NC;
    const int tid = threadIdx.x;
    const int base_l = b * L_ + c * CH;
    const uint32_t sb = smem_u32(sm);
    float* cumA_sh = (float*)(sm + ST_CUMA);
    float* ws_sh = (float*)(sm + ST_WS);
    float* Bstg = (float*)(sm + ST_BSTG);
    float* xstg = (float*)(sm + ST_XSTG);

    cumA_sh[tid] = g_cumA[blk * CH + tid];
    __syncthreads();
    ws_sh[tid] = g_dt[(base_l + tid) * NH + h] * __expf(cumA_sh[CH - 1] - cumA_sh[tid]);
    __syncthreads();

    const int warp = tid >> 5, lane = tid & 31;
    const int warp_m = warp & 1, warp_n = warp >> 1;
    const int lrow = (lane & 7) + ((lane >> 3) & 1) * 8;
    const int lhalf = lane >> 4;

    float acc[2][4][4];
#pragma unroll
    for (int a = 0; a < 2; a++)
#pragma unroll
        for (int bq = 0; bq < 4; bq++)
#pragma unroll
            for (int cq = 0; cq < 4; cq++) acc[a][bq][cq] = 0.f;

    for (int s0 = 0; s0 < CH; s0 += 32) {
#pragma unroll
        for (int ii = 0; ii < 16; ii++) {
            const int i = tid + ii * 256;
            const int s = i >> 7, n = i & 127;
            Bstg[s * 129 + n] = g_xBC[(size_t)(base_l + s0 + s) * CD + DSSM + n];
        }
#pragma unroll
        for (int ii = 0; ii < 8; ii++) {
            const int i = tid + ii * 256;
            const int s = i >> 6, p = i & 63;
            xstg[s * 65 + p] = g_xBC[(size_t)(base_l + s0 + s) * CD + h * HD + p];
        }
        __syncthreads();
#pragma unroll
        for (int jj = 0; jj < 8; jj++) {
            const int j = tid + jj * 256;              // 2048
            const int n = j >> 4, sl = (j & 15) * 2;
            uint32_t hi, lo;
            split2(Bstg[sl * 129 + n], Bstg[(sl + 1) * 129 + n], hi, lo);
            const uint32_t a = (uint32_t)(n * 64) + CSWZ(n, sl >> 3) + (sl & 7) * 2;
            *(uint32_t*)(sm + ST_B + a) = hi;
            *(uint32_t*)(sm + ST_BLO + a) = lo;
        }
#pragma unroll
        for (int jj = 0; jj < 4; jj++) {
            const int j = tid + jj * 256;              // 1024
            const int p = j >> 4, sl = (j & 15) * 2;
            uint32_t hi, lo;
            split2(xstg[sl * 65 + p] * ws_sh[s0 + sl],
                   xstg[(sl + 1) * 65 + p] * ws_sh[s0 + sl + 1], hi, lo);
            const uint32_t a = (uint32_t)(p * 64) + CSWZ(p, sl >> 3) + (sl & 7) * 2;
            *(uint32_t*)(sm + ST_A + a) = hi;
            *(uint32_t*)(sm + ST_ALO + a) = lo;
        }
        __syncthreads();
#pragma unroll
        for (int ki = 0; ki < 2; ki++) {
            const int chunk = ki * 2 + lhalf;
            uint32_t ah[2][4], al[2][4];
#pragma unroll
            for (int mi = 0; mi < 2; mi++) {
                const int r = warp_m * 32 + mi * 16 + lrow;
                const uint32_t off = (uint32_t)(r * 64) + CSWZ(r, chunk);
                ldm4(ah[mi], sb + ST_A + off);
                ldm4(al[mi], sb + ST_ALO + off);
            }
            uint32_t bh[2][4], bl[2][4];
#pragma unroll
            for (int nj = 0; nj < 2; nj++) {
                const int r = warp_n * 32 + nj * 16 + lrow;
                const uint32_t off = (uint32_t)(r * 64) + CSWZ(r, chunk);
                ldm4(bh[nj], sb + ST_B + off);
                ldm4(bl[nj], sb + ST_BLO + off);
            }
#pragma unroll
            for (int mi = 0; mi < 2; mi++)
#pragma unroll
                for (int nj = 0; nj < 4; nj++) {
                    const int g = nj >> 1, hh = nj & 1;
                    mma16816(acc[mi][nj], ah[mi], bh[g][hh], bh[g][hh + 2]);
                    mma16816(acc[mi][nj], ah[mi], bl[g][hh], bl[g][hh + 2]);
                    mma16816(acc[mi][nj], al[mi], bh[g][hh], bh[g][hh + 2]);
                }
        }
        __syncthreads();
    }

#pragma unroll
    for (int mi = 0; mi < 2; mi++)
#pragma unroll
        for (int nj = 0; nj < 4; nj++) {
            const int row = warp_m * 32 + mi * 16 + (lane >> 2);
            const int col = warp_n * 32 + nj * 8 + (lane & 3) * 2;
            float* dst = &g_states[(size_t)blk * HD * DS + (size_t)row * DS + col];
            *(float2*)dst = make_float2(acc[mi][nj][0], acc[mi][nj][1]);
            *(float2*)(dst + 8 * DS) = make_float2(acc[mi][nj][2], acc[mi][nj][3]);
        }
}

// ---------------- inter-chunk recurrence (sequential over chunks) --------
__global__ __launch_bounds__(256) void kernel_scan() {
    const int b = blockIdx.x >> 5;
    const int h = blockIdx.x & 31;
    const int tid = threadIdx.x;
    float4 prev[8];
#pragma unroll
    for (int i = 0; i < 8; i++) prev[i] = make_float4(0.f, 0.f, 0.f, 0.f);
    for (int c = 0; c < NC; c++) {
        int blk = (b * NC + c) * NH + h;
        float cd = __expf(g_cumA[blk * CH + CH - 1]);
        const float4* st = (const float4*)&g_states[(size_t)blk * HD * DS];
        float4* pv = (float4*)&g_prev[(size_t)blk * HD * DS];
#pragma unroll
        for (int i = 0; i < 8; i++) {
            float4 s = st[tid + i * 256];
            float4 pr = prev[i];
            pv[tid + i * 256] = pr;
            prev[i] = make_float4(pr.x * cd + s.x, pr.y * cd + s.y,
                                  pr.z * cd + s.z, pr.w * cd + s.w);
        }
    }
}

// ---------------- fused Yd + Yoff + D*x on HMMA --------------------------
// Warp w owns row slabs rb0=w*16 and rb1=240-w*16 (balances the triangle).
#define YO_CUMA  0
#define YO_DT    1024
#define YO_EA    2048
#define YO_W     3072                    // 16KB [256][64B]
#define YO_WLO   19456
#define YO_XT    35840                   // 4KB [64][64B]
#define YO_XTLO  39936
#define YO_STAGE 44032                   // [32][65] fp32 = 8320 B
#define YO_SMEM  52352

__global__ __launch_bounds__(256) void kernel_ydoff_mma(const float* __restrict__ Dv) {
    extern __shared__ __align__(1024) char sm[];
    const int blk = blockIdx.x;
    const int h = blk & (NH - 1);
    const int bc = blk / NH;
    const int b = bc / NC, c = bc - b * NC;
    const int tid = threadIdx.x;
    const int base_l = b * L_ + c * CH;
    const uint32_t sb = smem_u32(sm);
    float* cumA_sh = (float*)(sm + YO_CUMA);
    float* dt_sh = (float*)(sm + YO_DT);
    float* eA_sh = (float*)(sm + YO_EA);
    float* stg = (float*)(sm + YO_STAGE);
    const float* Gb = g_G + (size_t)bc * CH * CH;

    cumA_sh[tid] = g_cumA[blk * CH + tid];
    dt_sh[tid] = g_dt[(base_l + tid) * NH + h];
    __syncthreads();
    eA_sh[tid] = __expf(cumA_sh[tid]);
    __syncthreads();

    const int warp = tid >> 5, lane = tid & 31;
    const int lrow = (lane & 7) + ((lane >> 3) & 1) * 8;
    const int lhalf = lane >> 4;
    const int rb0 = warp * 16;
    const int rb1 = 240 - warp * 16;

    float acc[2][8][4];
#pragma unroll
    for (int a = 0; a < 2; a++)
#pragma unroll
        for (int bq = 0; bq < 8; bq++)
#pragma unroll
            for (int cq = 0; cq < 4; cq++) acc[a][bq][cq] = 0.f;

    // ---- phase 1: Yd over s-chunks (triangular) ----
    for (int s0 = 0; s0 < CH; s0 += 32) {
#pragma unroll
        for (int ii = 0; ii < 8; ii++) {
            const int i = tid + ii * 256;
            const int s = i >> 6, p = i & 63;
            stg[s * 65 + p] = g_xBC[(size_t)(base_l + s0 + s) * CD + h * HD + p];
        }
        __syncthreads();
        // W rows t >= s0 only (rows < s0 are never read by active slabs)
        const int nent = (CH - s0) * 16;
        for (int j = tid; j < nent; j += 256) {
            const int t = s0 + (j >> 4), sl = (j & 15) * 2;
            const int sg = s0 + sl;
            const float cat = cumA_sh[t];
            float w0 = (t >= sg) ? Gb[t * CH + sg] * __expf(cat - cumA_sh[sg]) * dt_sh[sg] : 0.f;
            float w1 = (t >= sg + 1) ? Gb[t * CH + sg + 1] * __expf(cat - cumA_sh[sg + 1]) * dt_sh[sg + 1] : 0.f;
            uint32_t hi, lo;
            split2(w0, w1, hi, lo);
            const uint32_t a = (uint32_t)(t * 64) + CSWZ(t, sl >> 3) + (sl & 7) * 2;
            *(uint32_t*)(sm + YO_W + a) = hi;
            *(uint32_t*)(sm + YO_WLO + a) = lo;
        }
        // xT[p][sl]
#pragma unroll
        for (int jj = 0; jj < 4; jj++) {
            const int j = tid + jj * 256;              // 1024
            const int p = j >> 4, sl = (j & 15) * 2;
            uint32_t hi, lo;
            split2(stg[sl * 65 + p], stg[(sl + 1) * 65 + p], hi, lo);
            const uint32_t a = (uint32_t)(p * 64) + CSWZ(p, sl >> 3) + (sl & 7) * 2;
            *(uint32_t*)(sm + YO_XT + a) = hi;
            *(uint32_t*)(sm + YO_XTLO + a) = lo;
        }
        __syncthreads();
        const bool act0 = (rb0 + 16 > s0);
        const bool act1 = (rb1 + 16 > s0);
        if (act0 || act1) {
#pragma unroll
            for (int ki = 0; ki < 2; ki++) {
                const int chunk = ki * 2 + lhalf;
                uint32_t bh[4][4], bl[4][4];
#pragma unroll
                for (int nj = 0; nj < 4; nj++) {
                    const int r = nj * 16 + lrow;
                    const uint32_t off = (uint32_t)(r * 64) + CSWZ(r, chunk);
                    ldm4(bh[nj], sb + YO_XT + off);
                    ldm4(bl[nj], sb + YO_XTLO + off);
                }
#pragma unroll
                for (int mi = 0; mi < 2; mi++) {
                    if (mi == 0 ? !act0 : !act1) continue;
                    const int r = (mi ? rb1 : rb0) + lrow;
                    const uint32_t off = (uint32_t)(r * 64) + CSWZ(r, chunk);
                    uint32_t ah[4], al[4];
                    ldm4(ah, sb + YO_W + off);
                    ldm4(al, sb + YO_WLO + off);
#pragma unroll
                    for (int nj = 0; nj < 8; nj++) {
                        const int g = nj >> 1, hh = nj & 1;
                        mma16816(acc[mi][nj], ah, bh[g][hh], bh[g][hh + 2]);
                        mma16816(acc[mi][nj], ah, bl[g][hh], bl[g][hh + 2]);
                        mma16816(acc[mi][nj], al, bh[g][hh], bh[g][hh + 2]);
                    }
                }
            }
        }
        __syncthreads();
    }

    // ---- phase 2: Yoff over n-chunks (dense) ----
    const float* prev_base = &g_prev[(size_t)blk * HD * DS];
    for (int n0 = 0; n0 < DS; n0 += 32) {
#pragma unroll
        for (int jj = 0; jj < 16; jj++) {
            const int j = tid + jj * 256;              // 4096
            const int t = j >> 4, nl = (j & 15) * 2;
            const float ea = eA_sh[t];
            const float* cp = &g_xBC[(size_t)(base_l + t) * CD + DSSM + DS + n0 + nl];
            uint32_t hi, lo;
            split2(cp[0] * ea, cp[1] * ea, hi, lo);
            const uint32_t a = (uint32_t)(t * 64) + CSWZ(t, nl >> 3) + (nl & 7) * 2;
            *(uint32_t*)(sm + YO_W + a) = hi;
            *(uint32_t*)(sm + YO_WLO + a) = lo;
        }
#pragma unroll
        for (int jj = 0; jj < 4; jj++) {
            const int j = tid + jj * 256;              // 1024
            const int p = j >> 4, nl = (j & 15) * 2;
            const float* pp = &prev_base[(size_t)p * DS + n0 + nl];
            uint32_t hi, lo;
            split2(pp[0], pp[1], hi, lo);
            const uint32_t a = (uint32_t)(p * 64) + CSWZ(p, nl >> 3) + (nl & 7) * 2;
            *(uint32_t*)(sm + YO_XT + a) = hi;
            *(uint32_t*)(sm + YO_XTLO + a) = lo;
        }
        __syncthreads();
#pragma unroll
        for (int ki = 0; ki < 2; ki++) {
            const int chunk = ki * 2 + lhalf;
            uint32_t bh[4][4], bl[4][4];
#pragma unroll
            for (int nj = 0; nj < 4; nj++) {
                const int r = nj * 16 + lrow;
                const uint32_t off = (uint32_t)(r * 64) + CSWZ(r, chunk);
                ldm4(bh[nj], sb + YO_XT + off);
                ldm4(bl[nj], sb + YO_XTLO + off);
            }
#pragma unroll
            for (int mi = 0; mi < 2; mi++) {
                const int r = (mi ? rb1 : rb0) + lrow;
                const uint32_t off = (uint32_t)(r * 64) + CSWZ(r, chunk);
                uint32_t ah[4], al[4];
                ldm4(ah, sb + YO_W + off);
                ldm4(al, sb + YO_WLO + off);
#pragma unroll
                for (int nj = 0; nj < 8; nj++) {
                    const int g = nj >> 1, hh = nj & 1;
                    mma16816(acc[mi][nj], ah, bh[g][hh], bh[g][hh + 2]);
                    mma16816(acc[mi][nj], ah, bl[g][hh], bl[g][hh + 2]);
                    mma16816(acc[mi][nj], al, bh[g][hh], bh[g][hh + 2]);
                }
            }
        }
        __syncthreads();
    }

    // ---- epilogue: + D[h]*x, write Y ----
    const float Dh = Dv[h];
#pragma unroll
    for (int mi = 0; mi < 2; mi++)
#pragma unroll
        for (int nj = 0; nj < 8; nj++) {
            const int row = (mi ? rb1 : rb0) + (lane >> 2);
            const int col = nj * 8 + (lane & 3) * 2;
            const size_t l0 = (size_t)(base_l + row);
            float2 x0 = *(const float2*)&g_xBC[l0 * CD + h * HD + col];
            float2 x1 = *(const float2*)&g_xBC[(l0 + 8) * CD + h * HD + col];
            *(float2*)&g_Y[l0 * DSSM + h * HD + col] =
                make_float2(acc[mi][nj][0] + Dh * x0.x, acc[mi][nj][1] + Dh * x0.y);
            *(float2*)&g_Y[(l0 + 8) * DSSM + h * HD + col] =
                make_float2(acc[mi][nj][2] + Dh * x1.x, acc[mi][nj][3] + Dh * x1.y);
        }
}

// ---------------- gated RMSNorm -> bf16 hi/lo ----------------
__global__ __launch_bounds__(256) void kernel_norm(const float* __restrict__ nw) {
    const int row = blockIdx.x;
    const int tid = threadIdx.x;
    const float* y = &g_Y[(size_t)row * DSSM];
    const float* z = &g_zx[(size_t)row * DIP];  // z = first DSSM cols
    float v[8];
    float sum = 0.f;
#pragma unroll
    for (int i = 0; i < 8; i++) {
        int cc = tid + i * 256;
        float zz = z[cc];
        float vv = y[cc] * (zz / (1.f + __expf(-zz)));
        v[i] = vv;
        sum += vv * vv;
    }
    __shared__ float red[256];
    red[tid] = sum;
    __syncthreads();
    for (int off = 128; off; off >>= 1) {
        if (tid < off) red[tid] += red[tid + off];
        __syncthreads();
    }
    const float scale = rsqrtf(red[0] * (1.f / DSSM) + 1e-5f);
#pragma unroll
    for (int i = 0; i < 8; i++) {
        int cc = tid + i * 256;
        float o = v[i] * scale * nw[cc];
        __nv_bfloat16 h = __float2bfloat16(o);
        g_ynh[(size_t)row * DSSM + cc] = h;
        g_ynl[(size_t)row * DSSM + cc] = __float2bfloat16(o - __bfloat162float(h));
    }
}

// ---------------- launch ----------------
extern "C" void kernel_launch(void* const* d_in, const int* in_sizes, int n_in,
                              void* d_out, int out_size) {
    const float* u     = (const float*)d_in[0];
    const int*   cidx  = (const int*)d_in[1];
    const float* W_in  = (const float*)d_in[2];
    const float* cw    = (const float*)d_in[3];
    const float* cb    = (const float*)d_in[4];
    const float* dtb   = (const float*)d_in[5];
    const float* A_log = (const float*)d_in[6];
    const float* Dv    = (const float*)d_in[7];
    const float* nw    = (const float*)d_in[8];
    const float* W_out = (const float*)d_in[9];
    float* out = (float*)d_out;

    float* zx_p;
    __nv_bfloat16 *uh, *ul, *wih, *wil, *woh, *wol, *ynh, *ynl;
    cudaGetSymbolAddress((void**)&zx_p, g_zx);
    cudaGetSymbolAddress((void**)&uh, g_uh);
    cudaGetSymbolAddress((void**)&ul, g_ul);
    cudaGetSymbolAddress((void**)&wih, g_wih);
    cudaGetSymbolAddress((void**)&wil, g_wil);
    cudaGetSymbolAddress((void**)&woh, g_woh);
    cudaGetSymbolAddress((void**)&wol, g_wol);
    cudaGetSymbolAddress((void**)&ynh, g_ynh);
    cudaGetSymbolAddress((void**)&ynl, g_ynl);

    cudaFuncSetAttribute(gemm_mma, cudaFuncAttributeMaxDynamicSharedMemorySize, GM_SMEM);
    cudaFuncSetAttribute(kernel_states_mma, cudaFuncAttributeMaxDynamicSharedMemorySize, ST_SMEM);
    cudaFuncSetAttribute(kernel_ydoff_mma, cudaFuncAttributeMaxDynamicSharedMemorySize, YO_SMEM);

    // 0) split fp32 -> bf16 hi/lo
    {
        int n4;
        n4 = (B_ * L_ * DM) / 4;
        split_bf16<<<(n4 + 255) / 256, 256>>>(u, uh, ul, n4);
        n4 = (DIP * DM) / 4;
        split_bf16<<<(n4 + 255) / 256, 256>>>(W_in, wih, wil, n4);
        n4 = (DM * DSSM) / 4;
        split_bf16<<<(n4 + 255) / 256, 256>>>(W_out, woh, wol, n4);
    }
    // 1) zxbcdt = u @ W_in^T   (M=4096, N=4384, K=1024) on HMMA
    gemm_mma<<<dim3((DIP + 127) / 128, (B_ * L_) / 128), 256, GM_SMEM>>>(
        uh, ul, wih, wil, zx_p, B_ * L_, DIP, DM);
    // 2) tree conv + silu + dt softplus
    kernel_conv<<<B_ * L_, 256>>>(cidx, cw, cb, dtb);
    // 3) cumsum(dt*A) per chunk/head
    kernel_cumA<<<B_ * NC * NH, 256>>>(A_log);
    // 4) G = C@B^T per (b,chunk), lower-triangle blocks only
    kernel_G<<<dim3(CH / 16, CH / 16, B_ * NC), dim3(16, 16)>>>();
    // 5) chunk end-states on HMMA
    kernel_states_mma<<<B_ * NC * NH, 256, ST_SMEM>>>();
    // 6) inter-chunk scan
    kernel_scan<<<B_ * NH, 256>>>();
    // 7) fused Yd + Yoff + D*x on HMMA (balanced triangular skip)
    kernel_ydoff_mma<<<B_ * NC * NH, 256, YO_SMEM>>>(Dv);
    // 8) gated RMSNorm -> bf16 hi/lo
    kernel_norm<<<B_ * L_, 256>>>(nw);
    // 9) out = yn @ W_out^T  (M=4096, N=1024, K=2048) on HMMA
    gemm_mma<<<dim3(DM / 128, (B_ * L_) / 128), 256, GM_SMEM>>>(
        ynh, ynl, woh, wol, out, B_ * L_, DM, DSSM);
}

// round 6
// speedup vs baseline: 3.9516x; 1.1339x over previous
#include <cuda_runtime.h>
#include <cuda_bf16.h>
#include <cuda_fp16.h>
#include <math.h>
#include <stdint.h>

#define B_   2
#define L_   2048
#define DM   1024
#define DIP  4384
#define DSSM 2048
#define CD   2304
#define NZX  (DSSM + CD)               /* 4352 = z | xBC, dt handled separately */
#define NH   32
#define HD   64
#define DS   128
#define CH   256
#define NC   8

// ---------------- scratch (device globals; no allocation) ----------------
__device__ float g_zx[B_ * L_ * NZX];          // in-proj output (z | xBC)
__device__ float g_xBC[B_ * L_ * CD];          // post-conv+silu (x | B | C)
__device__ float g_dt[B_ * L_ * NH];           // softplus dt (computed in fp32)
__device__ float g_G[B_ * NC * CH * CH];       // per-chunk C@B^T (head-independent)
__device__ float g_cumA[B_ * NC * NH * CH];    // inclusive cumsum of dt*A per chunk
__device__ float g_states[B_ * NC * NH * HD * DS];
__device__ float g_prev[B_ * NC * NH * HD * DS];
__device__ float g_Y[B_ * L_ * DSSM];

// fp16 operand buffers for the two projection GEMMs
__device__ __half g_uh[B_ * L_ * DM];
__device__ __half g_ul[B_ * L_ * DM];
__device__ __half g_wih[DIP * DM];             // W_in single fp16
__device__ __half g_woh[DM * DSSM];            // W_out single fp16
__device__ __half g_ynh[B_ * L_ * DSSM];
__device__ __half g_ynl[B_ * L_ * DSSM];

// ---------------- warp-level MMA helpers (arch-neutral PTX) ----------------
__device__ __forceinline__ uint32_t smem_u32(const void* p) {
    uint32_t a;
    asm("{ .reg .u64 t; cvta.to.shared.u64 t, %1; cvt.u32.u64 %0, t; }" : "=r"(a) : "l"(p));
    return a;
}
__device__ __forceinline__ void ldm4(uint32_t* r, uint32_t addr) {
    asm volatile("ldmatrix.sync.aligned.m8n8.x4.shared.b16 {%0,%1,%2,%3}, [%4];"
                 : "=r"(r[0]), "=r"(r[1]), "=r"(r[2]), "=r"(r[3]) : "r"(addr));
}
__device__ __forceinline__ void mma16816(float* d, const uint32_t* a,
                                         uint32_t b0, uint32_t b1) {
    asm volatile(
        "mma.sync.aligned.m16n8k16.row.col.f32.bf16.bf16.f32 "
        "{%0,%1,%2,%3}, {%4,%5,%6,%7}, {%8,%9}, {%0,%1,%2,%3};"
        : "+f"(d[0]), "+f"(d[1]), "+f"(d[2]), "+f"(d[3])
        : "r"(a[0]), "r"(a[1]), "r"(a[2]), "r"(a[3]), "r"(b0), "r"(b1));
}
__device__ __forceinline__ void mma16816h(float* d, const uint32_t* a,
                                          uint32_t b0, uint32_t b1) {
    asm volatile(
        "mma.sync.aligned.m16n8k16.row.col.f32.f16.f16.f32 "
        "{%0,%1,%2,%3}, {%4,%5,%6,%7}, {%8,%9}, {%0,%1,%2,%3};"
        : "+f"(d[0]), "+f"(d[1]), "+f"(d[2]), "+f"(d[3])
        : "r"(a[0]), "r"(a[1]), "r"(a[2]), "r"(a[3]), "r"(b0), "r"(b1));
}
__device__ __forceinline__ void cpasync16(uint32_t dst, const void* src, int sz) {
    asm volatile("cp.async.cg.shared.global [%0], [%1], 16, %2;"
                 :: "r"(dst), "l"(src), "r"(sz) : "memory");
}
#define CP_COMMIT() asm volatile("cp.async.commit_group;" ::: "memory")
#define CP_WAIT0()  asm volatile("cp.async.wait_group 0;" ::: "memory")
#define CP_WAIT1()  asm volatile("cp.async.wait_group 1;" ::: "memory")

// chunk swizzle for 64-byte rows: conflict-free 8-row ldmatrix gathers
#define CSWZ(r, c) ((((c) ^ (((r) >> 1) & 3))) << 4)

// pack two fp32 into bf16x2 hi word + bf16x2 lo-correction word
__device__ __forceinline__ void split2(float a, float b, uint32_t& hi, uint32_t& lo) {
    __nv_bfloat16 ha = __float2bfloat16(a), hb = __float2bfloat16(b);
    __nv_bfloat16 la = __float2bfloat16(a - __bfloat162float(ha));
    __nv_bfloat16 lb = __float2bfloat16(b - __bfloat162float(hb));
    __nv_bfloat162 H{ha, hb}, L{la, lb};
    hi = *(uint32_t*)&H;
    lo = *(uint32_t*)&L;
}

// ---------------- fp32 -> fp16 hi/lo split & single convert ----------------
__global__ __launch_bounds__(256) void split_fp16(const float* __restrict__ src,
                                                  __half* __restrict__ hi,
                                                  __half* __restrict__ lo,
                                                  int n4) {
    int i = blockIdx.x * 256 + threadIdx.x;
    if (i >= n4) return;
    float4 v = ((const float4*)src)[i];
    __half h0 = __float2half_rn(v.x), h1 = __float2half_rn(v.y);
    __half h2 = __float2half_rn(v.z), h3 = __float2half_rn(v.w);
    __half l0 = __float2half_rn(v.x - __half2float(h0));
    __half l1 = __float2half_rn(v.y - __half2float(h1));
    __half l2 = __float2half_rn(v.z - __half2float(h2));
    __half l3 = __float2half_rn(v.w - __half2float(h3));
    __half2 H0{h0, h1}, H1{h2, h3}, L0{l0, l1}, L1{l2, l3};
    ((__half2*)hi)[2 * i + 0] = H0;
    ((__half2*)hi)[2 * i + 1] = H1;
    ((__half2*)lo)[2 * i + 0] = L0;
    ((__half2*)lo)[2 * i + 1] = L1;
}
__global__ __launch_bounds__(256) void cvt_fp16(const float* __restrict__ src,
                                                __half* __restrict__ dst, int n4) {
    int i = blockIdx.x * 256 + threadIdx.x;
    if (i >= n4) return;
    float4 v = ((const float4*)src)[i];
    __half2 H0{__float2half_rn(v.x), __float2half_rn(v.y)};
    __half2 H1{__float2half_rn(v.z), __float2half_rn(v.w)};
    ((__half2*)dst)[2 * i + 0] = H0;
    ((__half2*)dst)[2 * i + 1] = H1;
}

// ---------------- fp16 one-sided-split HMMA GEMM: C = A @ B^T -------------
// A in fp16 hi+lo (exact), B single fp16. 2 MMAs per fragment pair.
// smem/stage: Ahi 8K | Alo 8K | B 8K = 24KB; 3 stages = 72KB.
#define GM_SMEM (3 * 24576)

__global__ __launch_bounds__(256, 2) void gemm_mma_f16(const __half* __restrict__ Ah,
                                                       const __half* __restrict__ Al,
                                                       const __half* __restrict__ Bh,
                                                       float* __restrict__ C,
                                                       int M, int N, int K, int ldc) {
    extern __shared__ __align__(1024) char sm[];
    const int tid = threadIdx.x;
    const int m0 = blockIdx.y * 128, n0 = blockIdx.x * 128;
    const uint32_t sb0 = smem_u32(sm);
    const int warp = tid >> 5, lane = tid & 31;
    const int warp_m = warp & 3, warp_n = warp >> 2;
    const int KT = K >> 5;

    float acc[2][8][4];
#pragma unroll
    for (int a = 0; a < 2; a++)
#pragma unroll
        for (int b = 0; b < 8; b++)
#pragma unroll
            for (int c = 0; c < 4; c++) acc[a][b][c] = 0.f;

    auto load_stage = [&](int kt, int s) {
        const uint32_t sb = sb0 + s * 24576;
        const int k0 = kt << 5;
#pragma unroll
        for (int ii = 0; ii < 2; ii++) {
            const int i = tid + ii * 256;
            const int r = i >> 2, c = i & 3;
            const uint32_t sw = (uint32_t)(r * 64) + CSWZ(r, c);
            const size_t ga = (size_t)(m0 + r) * K + k0 + c * 8;
            cpasync16(sb + sw, Ah + ga, 16);
            cpasync16(sb + 8192 + sw, Al + ga, 16);
            const int rb = (n0 + r < N) ? (n0 + r) : (N - 1);
            const int bs = (n0 + r < N) ? 16 : 0;
            const size_t gb = (size_t)rb * K + k0 + c * 8;
            cpasync16(sb + 16384 + sw, Bh + gb, bs);
        }
    };

    load_stage(0, 0);
    CP_COMMIT();
    if (KT > 1) {
        load_stage(1, 1);
        CP_COMMIT();
    }

    const int lrow = (lane & 7) + ((lane >> 3) & 1) * 8;
    const int lhalf = lane >> 4;

    for (int kt = 0; kt < KT; kt++) {
        if (kt + 1 < KT) CP_WAIT1(); else CP_WAIT0();
        __syncthreads();
        if (kt + 2 < KT) {
            load_stage(kt + 2, (kt + 2) % 3);
            CP_COMMIT();
        }

        const uint32_t sb = sb0 + (kt % 3) * 24576;
#pragma unroll
        for (int ki = 0; ki < 2; ki++) {
            const int chunk = ki * 2 + lhalf;
            uint32_t ah[2][4], al[2][4];
#pragma unroll
            for (int mi = 0; mi < 2; mi++) {
                const int r = warp_m * 32 + mi * 16 + lrow;
                const uint32_t off = (uint32_t)(r * 64) + CSWZ(r, chunk);
                ldm4(ah[mi], sb + off);
                ldm4(al[mi], sb + 8192 + off);
            }
            uint32_t bh[4][4];
#pragma unroll
            for (int nj = 0; nj < 4; nj++) {
                const int r = warp_n * 64 + nj * 16 + lrow;
                const uint32_t off = (uint32_t)(r * 64) + CSWZ(r, chunk);
                ldm4(bh[nj], sb + 16384 + off);
            }
#pragma unroll
            for (int mi = 0; mi < 2; mi++)
#pragma unroll
                for (int nj = 0; nj < 8; nj++) {
                    const int g = nj >> 1, h = nj & 1;
                    mma16816h(acc[mi][nj], ah[mi], bh[g][h], bh[g][h + 2]);
                    mma16816h(acc[mi][nj], al[mi], bh[g][h], bh[g][h + 2]);
                }
        }
    }

#pragma unroll
    for (int mi = 0; mi < 2; mi++)
#pragma unroll
        for (int nj = 0; nj < 8; nj++) {
            const int row = m0 + warp_m * 32 + mi * 16 + (lane >> 2);
            const int col = n0 + warp_n * 64 + nj * 8 + (lane & 3) * 2;
            if (col < N) {
                float2 v0 = make_float2(acc[mi][nj][0], acc[mi][nj][1]);
                float2 v1 = make_float2(acc[mi][nj][2], acc[mi][nj][3]);
                *(float2*)&C[(size_t)row * ldc + col] = v0;
                *(float2*)&C[(size_t)(row + 8) * ldc + col] = v1;
            }
        }
}

// ---------------- exact fp32 dt: softplus(u @ W_dt^T + bias) -------------
__global__ __launch_bounds__(256) void kernel_dt(const float* __restrict__ u,
                                                 const float* __restrict__ W_in,
                                                 const float* __restrict__ dtb) {
    __shared__ float ush[64 * 68];
    __shared__ float wsh[32 * 68];
    const int tid = threadIdx.x;
    const int row0 = blockIdx.x * 64;
    const int col = tid & 31, r0 = (tid >> 5) * 8;
    float acc[8];
#pragma unroll
    for (int j = 0; j < 8; j++) acc[j] = 0.f;

    for (int k0 = 0; k0 < DM; k0 += 64) {
#pragma unroll
        for (int ii = 0; ii < 4; ii++) {
            const int i = tid + ii * 256;
            const int r = i >> 4, c = (i & 15) * 4;
            *(float4*)&ush[r * 68 + c] = *(const float4*)&u[(size_t)(row0 + r) * DM + k0 + c];
        }
#pragma unroll
        for (int ii = 0; ii < 2; ii++) {
            const int i = tid + ii * 256;
            const int r = i >> 4, c = (i & 15) * 4;
            *(float4*)&wsh[r * 68 + c] =
                *(const float4*)&W_in[(size_t)(NZX + r) * DM + k0 + c];
        }
        __syncthreads();
#pragma unroll 8
        for (int k = 0; k < 64; k++) {
            const float w = wsh[col * 68 + k];
#pragma unroll
            for (int j = 0; j < 8; j++) acc[j] += ush[(r0 + j) * 68 + k] * w;
        }
        __syncthreads();
    }
    const float bias = dtb[col];
#pragma unroll
    for (int j = 0; j < 8; j++) {
        float x = acc[j] + bias;
        g_dt[(row0 + r0 + j) * NH + col] = (x > 20.f) ? x : log1pf(expf(x));
    }
}

// ---------------- tree conv + silu ----------------
__global__ __launch_bounds__(256) void kernel_conv(const int* __restrict__ cidx,
                                                   const float* __restrict__ cw,
                                                   const float* __restrict__ cb) {
    const int bt = blockIdx.x;           // b*L_ + t
    const int b = bt / L_, t = bt - b * L_;
    const int tid = threadIdx.x;

    __shared__ int idx[4];
    if (tid < 4) idx[tid] = cidx[(size_t)b * 4 * L_ + 4 * t + tid];
    __syncthreads();
    const int i0 = idx[0], i1 = idx[1], i2 = idx[2], i3 = idx[3];

    for (int c = tid; c < CD; c += 256) {
        float acc = cb[c];
        const float* w = cw + c * 4;
        if (i0) acc += g_zx[(size_t)(b * L_ + i0 - 1) * NZX + DSSM + c] * w[0];
        if (i1) acc += g_zx[(size_t)(b * L_ + i1 - 1) * NZX + DSSM + c] * w[1];
        if (i2) acc += g_zx[(size_t)(b * L_ + i2 - 1) * NZX + DSSM + c] * w[2];
        if (i3) acc += g_zx[(size_t)(b * L_ + i3 - 1) * NZX + DSSM + c] * w[3];
        g_xBC[(size_t)bt * CD + c] = acc / (1.f + __expf(-acc));   // silu
    }
}

// ---------------- per-(b,c,h) inclusive cumsum of dt*A ----------------
__global__ __launch_bounds__(256) void kernel_cumA(const float* __restrict__ A_log) {
    const int blk = blockIdx.x;                 // (b*NC+c)*NH + h
    const int h = blk & (NH - 1);
    const int bc = blk / NH;
    const int b = bc / NC, c = bc - b * NC;
    const int t = threadIdx.x;
    const float Ah = -expf(A_log[h]);
    const int l = b * L_ + c * CH + t;
    __shared__ float s[CH];
    s[t] = g_dt[l * NH + h] * Ah;
    __syncthreads();
    for (int off = 1; off < CH; off <<= 1) {
        float add = (t >= off) ? s[t - off] : 0.f;
        __syncthreads();
        s[t] += add;
        __syncthreads();
    }
    g_cumA[blk * CH + t] = s[t];
}

// ---------------- G = C @ B^T per (b,chunk): lower-triangle blocks only --
__global__ void kernel_G() {
    const int bc = blockIdx.z;                 // b*NC + c
    const int t0 = blockIdx.y * 16, s0 = blockIdx.x * 16;
    if (t0 + 16 <= s0) return;                 // upper triangle never read
    const int tx = threadIdx.x, ty = threadIdx.y;
    const int tid = ty * 16 + tx;
    __shared__ float Cs[16][129];
    __shared__ float Bs[16][129];
    const int b = bc / NC, c = bc - b * NC;
    const int base_l = b * L_ + c * CH;
    for (int i = tid; i < 16 * 128; i += 256) {
        int row = i >> 7, n = i & 127;
        Cs[row][n] = g_xBC[(size_t)(base_l + t0 + row) * CD + DSSM + DS + n];
        Bs[row][n] = g_xBC[(size_t)(base_l + s0 + row) * CD + DSSM + n];
    }
    __syncthreads();
    float acc = 0.f;
#pragma unroll 8
    for (int n = 0; n < 128; n++) acc += Cs[ty][n] * Bs[tx][n];
    g_G[((size_t)bc * CH + t0 + ty) * CH + s0 + tx] = acc;
}

// ---------------- states on HMMA: S[p,n] = sum_s ws[s]*x[s,p]*B[s,n] -----
#define ST_CUMA 0
#define ST_WS   1024
#define ST_A    2048
#define ST_ALO  6144
#define ST_B    10240
#define ST_BLO  18432
#define ST_BSTG 26624                    // [32][129] fp32 = 16512 B
#define ST_XSTG 43136                    // [32][65]  fp32 = 8320 B
#define ST_SMEM 51456

__global__ __launch_bounds__(256) void kernel_states_mma() {
    extern __shared__ __align__(1024) char sm[];
    const int blk = blockIdx.x;
    const int h = blk & (NH - 1);
    const int bc = blk / NH;
    const int b = bc / NC, c = bc - b * NC;
    const int tid = threadIdx.x;
    const int base_l = b * L_ + c * CH;
    const uint32_t sb = smem_u32(sm);
    float* cumA_sh = (float*)(sm + ST_CUMA);
    float* ws_sh = (float*)(sm + ST_WS);
    float* Bstg = (float*)(sm + ST_BSTG);
    float* xstg = (float*)(sm + ST_XSTG);

    cumA_sh[tid] = g_cumA[blk * CH + tid];
    __syncthreads();
    ws_sh[tid] = g_dt[(base_l + tid) * NH + h] * __expf(cumA_sh[CH - 1] - cumA_sh[tid]);
    __syncthreads();

    const int warp = tid >> 5, lane = tid & 31;
    const int warp_m = warp & 1, warp_n = warp >> 1;
    const int lrow = (lane & 7) + ((lane >> 3) & 1) * 8;
    const int lhalf = lane >> 4;

    float acc[2][4][4];
#pragma unroll
    for (int a = 0; a < 2; a++)
#pragma unroll
        for (int bq = 0; bq < 4; bq++)
#pragma unroll
            for (int cq = 0; cq < 4; cq++) acc[a][bq][cq] = 0.f;

    for (int s0 = 0; s0 < CH; s0 += 32) {
#pragma unroll
        for (int ii = 0; ii < 16; ii++) {
            const int i = tid + ii * 256;
            const int s = i >> 7, n = i & 127;
            Bstg[s * 129 + n] = g_xBC[(size_t)(base_l + s0 + s) * CD + DSSM + n];
        }
#pragma unroll
        for (int ii = 0; ii < 8; ii++) {
            const int i = tid + ii * 256;
            const int s = i >> 6, p = i & 63;
            xstg[s * 65 + p] = g_xBC[(size_t)(base_l + s0 + s) * CD + h * HD + p];
        }
        __syncthreads();
#pragma unroll
        for (int jj = 0; jj < 8; jj++) {
            const int j = tid + jj * 256;              // 2048
            const int n = j >> 4, sl = (j & 15) * 2;
            uint32_t hi, lo;
            split2(Bstg[sl * 129 + n], Bstg[(sl + 1) * 129 + n], hi, lo);
            const uint32_t a = (uint32_t)(n * 64) + CSWZ(n, sl >> 3) + (sl & 7) * 2;
            *(uint32_t*)(sm + ST_B + a) = hi;
            *(uint32_t*)(sm + ST_BLO + a) = lo;
        }
#pragma unroll
        for (int jj = 0; jj < 4; jj++) {
            const int j = tid + jj * 256;              // 1024
            const int p = j >> 4, sl = (j & 15) * 2;
            uint32_t hi, lo;
            split2(xstg[sl * 65 + p] * ws_sh[s0 + sl],
                   xstg[(sl + 1) * 65 + p] * ws_sh[s0 + sl + 1], hi, lo);
            const uint32_t a = (uint32_t)(p * 64) + CSWZ(p, sl >> 3) + (sl & 7) * 2;
            *(uint32_t*)(sm + ST_A + a) = hi;
            *(uint32_t*)(sm + ST_ALO + a) = lo;
        }
        __syncthreads();
#pragma unroll
        for (int ki = 0; ki < 2; ki++) {
            const int chunk = ki * 2 + lhalf;
            uint32_t ah[2][4], al[2][4];
#pragma unroll
            for (int mi = 0; mi < 2; mi++) {
                const int r = warp_m * 32 + mi * 16 + lrow;
                const uint32_t off = (uint32_t)(r * 64) + CSWZ(r, chunk);
                ldm4(ah[mi], sb + ST_A + off);
                ldm4(al[mi], sb + ST_ALO + off);
            }
            uint32_t bh[2][4], bl[2][4];
#pragma unroll
            for (int nj = 0; nj < 2; nj++) {
                const int r = warp_n * 32 + nj * 16 + lrow;
                const uint32_t off = (uint32_t)(r * 64) + CSWZ(r, chunk);
                ldm4(bh[nj], sb + ST_B + off);
                ldm4(bl[nj], sb + ST_BLO + off);
            }
#pragma unroll
            for (int mi = 0; mi < 2; mi++)
#pragma unroll
                for (int nj = 0; nj < 4; nj++) {
                    const int g = nj >> 1, hh = nj & 1;
                    mma16816(acc[mi][nj], ah[mi], bh[g][hh], bh[g][hh + 2]);
                    mma16816(acc[mi][nj], ah[mi], bl[g][hh], bl[g][hh + 2]);
                    mma16816(acc[mi][nj], al[mi], bh[g][hh], bh[g][hh + 2]);
                }
        }
        __syncthreads();
    }

#pragma unroll
    for (int mi = 0; mi < 2; mi++)
#pragma unroll
        for (int nj = 0; nj < 4; nj++) {
            const int row = warp_m * 32 + mi * 16 + (lane >> 2);
            const int col = warp_n * 32 + nj * 8 + (lane & 3) * 2;
            float* dst = &g_states[(size_t)blk * HD * DS + (size_t)row * DS + col];
            *(float2*)dst = make_float2(acc[mi][nj][0], acc[mi][nj][1]);
            *(float2*)(dst + 8 * DS) = make_float2(acc[mi][nj][2], acc[mi][nj][3]);
        }
}

// ---------------- inter-chunk recurrence (sequential over chunks) --------
__global__ __launch_bounds__(256) void kernel_scan() {
    const int b = blockIdx.x >> 5;
    const int h = blockIdx.x & 31;
    const int tid = threadIdx.x;
    float4 prev[8];
#pragma unroll
    for (int i = 0; i < 8; i++) prev[i] = make_float4(0.f, 0.f, 0.f, 0.f);
    for (int c = 0; c < NC; c++) {
        int blk = (b * NC + c) * NH + h;
        float cd = __expf(g_cumA[blk * CH + CH - 1]);
        const float4* st = (const float4*)&g_states[(size_t)blk * HD * DS];
        float4* pv = (float4*)&g_prev[(size_t)blk * HD * DS];
#pragma unroll
        for (int i = 0; i < 8; i++) {
            float4 s = st[tid + i * 256];
            float4 pr = prev[i];
            pv[tid + i * 256] = pr;
            prev[i] = make_float4(pr.x * cd + s.x, pr.y * cd + s.y,
                                  pr.z * cd + s.z, pr.w * cd + s.w);
        }
    }
}

// ---------------- fused Yd + Yoff + D*x on HMMA --------------------------
// Warp w owns row slabs rb0=w*16 and rb1=240-w*16 (balances the triangle).
#define YO_CUMA  0
#define YO_DT    1024
#define YO_EA    2048
#define YO_W     3072                    // 16KB [256][64B]
#define YO_WLO   19456
#define YO_XT    35840                   // 4KB [64][64B]
#define YO_XTLO  39936
#define YO_STAGE 44032                   // [32][65] fp32 = 8320 B
#define YO_SMEM  52352

__global__ __launch_bounds__(256) void kernel_ydoff_mma(const float* __restrict__ Dv) {
    extern __shared__ __align__(1024) char sm[];
    const int blk = blockIdx.x;
    const int h = blk & (NH - 1);
    const int bc = blk / NH;
    const int b = bc / NC, c = bc - b * NC;
    const int tid = threadIdx.x;
    const int base_l = b * L_ + c * CH;
    const uint32_t sb = smem_u32(sm);
    float* cumA_sh = (float*)(sm + YO_CUMA);
    float* dt_sh = (float*)(sm + YO_DT);
    float* eA_sh = (float*)(sm + YO_EA);
    float* stg = (float*)(sm + YO_STAGE);
    const float* Gb = g_G + (size_t)bc * CH * CH;

    cumA_sh[tid] = g_cumA[blk * CH + tid];
    dt_sh[tid] = g_dt[(base_l + tid) * NH + h];
    __syncthreads();
    eA_sh[tid] = __expf(cumA_sh[tid]);
    __syncthreads();

    const int warp = tid >> 5, lane = tid & 31;
    const int lrow = (lane & 7) + ((lane >> 3) & 1) * 8;
    const int lhalf = lane >> 4;
    const int rb0 = warp * 16;
    const int rb1 = 240 - warp * 16;

    float acc[2][8][4];
#pragma unroll
    for (int a = 0; a < 2; a++)
#pragma unroll
        for (int bq = 0; bq < 8; bq++)
#pragma unroll
            for (int cq = 0; cq < 4; cq++) acc[a][bq][cq] = 0.f;

    // ---- phase 1: Yd over s-chunks (triangular) ----
    for (int s0 = 0; s0 < CH; s0 += 32) {
#pragma unroll
        for (int ii = 0; ii < 8; ii++) {
            const int i = tid + ii * 256;
            const int s = i >> 6, p = i & 63;
            stg[s * 65 + p] = g_xBC[(size_t)(base_l + s0 + s) * CD + h * HD + p];
        }
        __syncthreads();
        // W rows t >= s0 only (rows < s0 are never read by active slabs)
        const int nent = (CH - s0) * 16;
        for (int j = tid; j < nent; j += 256) {
            const int t = s0 + (j >> 4), sl = (j & 15) * 2;
            const int sg = s0 + sl;
            const float cat = cumA_sh[t];
            float w0 = (t >= sg) ? Gb[t * CH + sg] * __expf(cat - cumA_sh[sg]) * dt_sh[sg] : 0.f;
            float w1 = (t >= sg + 1) ? Gb[t * CH + sg + 1] * __expf(cat - cumA_sh[sg + 1]) * dt_sh[sg + 1] : 0.f;
            uint32_t hi, lo;
            split2(w0, w1, hi, lo);
            const uint32_t a = (uint32_t)(t * 64) + CSWZ(t, sl >> 3) + (sl & 7) * 2;
            *(uint32_t*)(sm + YO_W + a) = hi;
            *(uint32_t*)(sm + YO_WLO + a) = lo;
        }
        // xT[p][sl]
#pragma unroll
        for (int jj = 0; jj < 4; jj++) {
            const int j = tid + jj * 256;              // 1024
            const int p = j >> 4, sl = (j & 15) * 2;
            uint32_t hi, lo;
            split2(stg[sl * 65 + p], stg[(sl + 1) * 65 + p], hi, lo);
            const uint32_t a = (uint32_t)(p * 64) + CSWZ(p, sl >> 3) + (sl & 7) * 2;
            *(uint32_t*)(sm + YO_XT + a) = hi;
            *(uint32_t*)(sm + YO_XTLO + a) = lo;
        }
        __syncthreads();
        const bool act0 = (rb0 + 16 > s0);
        const bool act1 = (rb1 + 16 > s0);
        if (act0 || act1) {
#pragma unroll
            for (int ki = 0; ki < 2; ki++) {
                const int chunk = ki * 2 + lhalf;
                uint32_t bh[4][4], bl[4][4];
#pragma unroll
                for (int nj = 0; nj < 4; nj++) {
                    const int r = nj * 16 + lrow;
                    const uint32_t off = (uint32_t)(r * 64) + CSWZ(r, chunk);
                    ldm4(bh[nj], sb + YO_XT + off);
                    ldm4(bl[nj], sb + YO_XTLO + off);
                }
#pragma unroll
                for (int mi = 0; mi < 2; mi++) {
                    if (mi == 0 ? !act0 : !act1) continue;
                    const int r = (mi ? rb1 : rb0) + lrow;
                    const uint32_t off = (uint32_t)(r * 64) + CSWZ(r, chunk);
                    uint32_t ah[4], al[4];
                    ldm4(ah, sb + YO_W + off);
                    ldm4(al, sb + YO_WLO + off);
#pragma unroll
                    for (int nj = 0; nj < 8; nj++) {
                        const int g = nj >> 1, hh = nj & 1;
                        mma16816(acc[mi][nj], ah, bh[g][hh], bh[g][hh + 2]);
                        mma16816(acc[mi][nj], ah, bl[g][hh], bl[g][hh + 2]);
                        mma16816(acc[mi][nj], al, bh[g][hh], bh[g][hh + 2]);
                    }
                }
            }
        }
        __syncthreads();
    }

    // ---- phase 2: Yoff over n-chunks (dense) ----
    const float* prev_base = &g_prev[(size_t)blk * HD * DS];
    for (int n0 = 0; n0 < DS; n0 += 32) {
#pragma unroll
        for (int jj = 0; jj < 16; jj++) {
            const int j = tid + jj * 256;              // 4096
            const int t = j >> 4, nl = (j & 15) * 2;
            const float ea = eA_sh[t];
            const float* cp = &g_xBC[(size_t)(base_l + t) * CD + DSSM + DS + n0 + nl];
            uint32_t hi, lo;
            split2(cp[0] * ea, cp[1] * ea, hi, lo);
            const uint32_t a = (uint32_t)(t * 64) + CSWZ(t, nl >> 3) + (nl & 7) * 2;
            *(uint32_t*)(sm + YO_W + a) = hi;
            *(uint32_t*)(sm + YO_WLO + a) = lo;
        }
#pragma unroll
        for (int jj = 0; jj < 4; jj++) {
            const int j = tid + jj * 256;              // 1024
            const int p = j >> 4, nl = (j & 15) * 2;
            const float* pp = &prev_base[(size_t)p * DS + n0 + nl];
            uint32_t hi, lo;
            split2(pp[0], pp[1], hi, lo);
            const uint32_t a = (uint32_t)(p * 64) + CSWZ(p, nl >> 3) + (nl & 7) * 2;
            *(uint32_t*)(sm + YO_XT + a) = hi;
            *(uint32_t*)(sm + YO_XTLO + a) = lo;
        }
        __syncthreads();
#pragma unroll
        for (int ki = 0; ki < 2; ki++) {
            const int chunk = ki * 2 + lhalf;
            uint32_t bh[4][4], bl[4][4];
#pragma unroll
            for (int nj = 0; nj < 4; nj++) {
                const int r = nj * 16 + lrow;
                const uint32_t off = (uint32_t)(r * 64) + CSWZ(r, chunk);
                ldm4(bh[nj], sb + YO_XT + off);
                ldm4(bl[nj], sb + YO_XTLO + off);
            }
#pragma unroll
            for (int mi = 0; mi < 2; mi++) {
                const int r = (mi ? rb1 : rb0) + lrow;
                const uint32_t off = (uint32_t)(r * 64) + CSWZ(r, chunk);
                uint32_t ah[4], al[4];
                ldm4(ah, sb + YO_W + off);
                ldm4(al, sb + YO_WLO + off);
#pragma unroll
                for (int nj = 0; nj < 8; nj++) {
                    const int g = nj >> 1, hh = nj & 1;
                    mma16816(acc[mi][nj], ah, bh[g][hh], bh[g][hh + 2]);
                    mma16816(acc[mi][nj], ah, bl[g][hh], bl[g][hh + 2]);
                    mma16816(acc[mi][nj], al, bh[g][hh], bh[g][hh + 2]);
                }
            }
        }
        __syncthreads();
    }

    // ---- epilogue: + D[h]*x, write Y ----
    const float Dh = Dv[h];
#pragma unroll
    for (int mi = 0; mi < 2; mi++)
#pragma unroll
        for (int nj = 0; nj < 8; nj++) {
            const int row = (mi ? rb1 : rb0) + (lane >> 2);
            const int col = nj * 8 + (lane & 3) * 2;
            const size_t l0 = (size_t)(base_l + row);
            float2 x0 = *(const float2*)&g_xBC[l0 * CD + h * HD + col];
            float2 x1 = *(const float2*)&g_xBC[(l0 + 8) * CD + h * HD + col];
            *(float2*)&g_Y[l0 * DSSM + h * HD + col] =
                make_float2(acc[mi][nj][0] + Dh * x0.x, acc[mi][nj][1] + Dh * x0.y);
            *(float2*)&g_Y[(l0 + 8) * DSSM + h * HD + col] =
                make_float2(acc[mi][nj][2] + Dh * x1.x, acc[mi][nj][3] + Dh * x1.y);
        }
}

// ---------------- gated RMSNorm -> fp16 hi/lo ----------------
__global__ __launch_bounds__(256) void kernel_norm(const float* __restrict__ nw) {
    const int row = blockIdx.x;
    const int tid = threadIdx.x;
    const float* y = &g_Y[(size_t)row * DSSM];
    const float* z = &g_zx[(size_t)row * NZX];  // z = first DSSM cols
    float v[8];
    float sum = 0.f;
#pragma unroll
    for (int i = 0; i < 8; i++) {
        int cc = tid + i * 256;
        float zz = z[cc];
        float vv = y[cc] * (zz / (1.f + __expf(-zz)));
        v[i] = vv;
        sum += vv * vv;
    }
    __shared__ float red[256];
    red[tid] = sum;
    __syncthreads();
    for (int off = 128; off; off >>= 1) {
        if (tid < off) red[tid] += red[tid + off];
        __syncthreads();
    }
    const float scale = rsqrtf(red[0] * (1.f / DSSM) + 1e-5f);
#pragma unroll
    for (int i = 0; i < 8; i++) {
        int cc = tid + i * 256;
        float o = v[i] * scale * nw[cc];
        __half hh = __float2half_rn(o);
        g_ynh[(size_t)row * DSSM + cc] = hh;
        g_ynl[(size_t)row * DSSM + cc] = __float2half_rn(o - __half2float(hh));
    }
}

// ---------------- launch ----------------
extern "C" void kernel_launch(void* const* d_in, const int* in_sizes, int n_in,
                              void* d_out, int out_size) {
    const float* u     = (const float*)d_in[0];
    const int*   cidx  = (const int*)d_in[1];
    const float* W_in  = (const float*)d_in[2];
    const float* cw    = (const float*)d_in[3];
    const float* cb    = (const float*)d_in[4];
    const float* dtb   = (const float*)d_in[5];
    const float* A_log = (const float*)d_in[6];
    const float* Dv    = (const float*)d_in[7];
    const float* nw    = (const float*)d_in[8];
    const float* W_out = (const float*)d_in[9];
    float* out = (float*)d_out;

    float* zx_p;
    __half *uh, *ul, *wih, *woh, *ynh, *ynl;
    cudaGetSymbolAddress((void**)&zx_p, g_zx);
    cudaGetSymbolAddress((void**)&uh, g_uh);
    cudaGetSymbolAddress((void**)&ul, g_ul);
    cudaGetSymbolAddress((void**)&wih, g_wih);
    cudaGetSymbolAddress((void**)&woh, g_woh);
    cudaGetSymbolAddress((void**)&ynh, g_ynh);
    cudaGetSymbolAddress((void**)&ynl, g_ynl);

    cudaFuncSetAttribute(gemm_mma_f16, cudaFuncAttributeMaxDynamicSharedMemorySize, GM_SMEM);
    cudaFuncSetAttribute(kernel_states_mma, cudaFuncAttributeMaxDynamicSharedMemorySize, ST_SMEM);
    cudaFuncSetAttribute(kernel_ydoff_mma, cudaFuncAttributeMaxDynamicSharedMemorySize, YO_SMEM);

    // 0) operand converts + exact fp32 dt
    {
        int n4;
        n4 = (B_ * L_ * DM) / 4;
        split_fp16<<<(n4 + 255) / 256, 256>>>(u, uh, ul, n4);
        n4 = (DIP * DM) / 4;
        cvt_fp16<<<(n4 + 255) / 256, 256>>>(W_in, wih, n4);
        n4 = (DM * DSSM) / 4;
        cvt_fp16<<<(n4 + 255) / 256, 256>>>(W_out, woh, n4);
        kernel_dt<<<(B_ * L_) / 64, 256>>>(u, W_in, dtb);
    }
    // 1) z|xBC = u @ W_in[0:4352]^T   (M=4096, N=4352, K=1024) on fp16 HMMA
    gemm_mma_f16<<<dim3(NZX / 128, (B_ * L_) / 128), 256, GM_SMEM>>>(
        uh, ul, wih, zx_p, B_ * L_, NZX, DM, NZX);
    // 2) tree conv + silu
    kernel_conv<<<B_ * L_, 256>>>(cidx, cw, cb);
    // 3) cumsum(dt*A) per chunk/head
    kernel_cumA<<<B_ * NC * NH, 256>>>(A_log);
    // 4) G = C@B^T per (b,chunk), lower-triangle blocks only
    kernel_G<<<dim3(CH / 16, CH / 16, B_ * NC), dim3(16, 16)>>>();
    // 5) chunk end-states on HMMA (bf16 split-3)
    kernel_states_mma<<<B_ * NC * NH, 256, ST_SMEM>>>();
    // 6) inter-chunk scan
    kernel_scan<<<B_ * NH, 256>>>();
    // 7) fused Yd + Yoff + D*x on HMMA (bf16 split-3, balanced triangular skip)
    kernel_ydoff_mma<<<B_ * NC * NH, 256, YO_SMEM>>>(Dv);
    // 8) gated RMSNorm -> fp16 hi/lo
    kernel_norm<<<B_ * L_, 256>>>(nw);
    // 9) out = yn @ W_out^T  (M=4096, N=1024, K=2048) on fp16 HMMA
    gemm_mma_f16<<<dim3(DM / 128, (B_ * L_) / 128), 256, GM_SMEM>>>(
        ynh, ynl, woh, out, B_ * L_, DM, DSSM, DM);
}

// round 7
// speedup vs baseline: 4.9074x; 1.2419x over previous
#include <cuda_runtime.h>
#include <cuda_bf16.h>
#include <cuda_fp16.h>
#include <math.h>
#include <stdint.h>

#define B_   2
#define L_   2048
#define DM   1024
#define DIP  4384
#define DSSM 2048
#define CD   2304
#define NZX  (DSSM + CD)               /* 4352 = z | xBC, dt handled separately */
#define NH   32
#define HD   64
#define DS   128
#define CH   256
#define NC   8

// ---------------- scratch (device globals; no allocation) ----------------
__device__ float g_zx[B_ * L_ * NZX];          // in-proj output (z | xBC)
__device__ float g_xBC[B_ * L_ * CD];          // post-conv+silu (x | B | C)
__device__ float g_dt[B_ * L_ * NH];           // softplus dt (computed in fp32)
__device__ float g_G[B_ * NC * CH * CH];       // per-chunk C@B^T (head-independent)
__device__ float g_cumA[B_ * NC * NH * CH];    // inclusive cumsum of dt*A per chunk
__device__ float g_states[B_ * NC * NH * HD * DS];
__device__ float g_prev[B_ * NC * NH * HD * DS];
__device__ float g_Y[B_ * L_ * DSSM];

// fp16 operand buffers for the two projection GEMMs
__device__ __half g_uh[B_ * L_ * DM];
__device__ __half g_ul[B_ * L_ * DM];
__device__ __half g_wih[DIP * DM];             // W_in single fp16
__device__ __half g_woh[DM * DSSM];            // W_out single fp16
__device__ __half g_ynh[B_ * L_ * DSSM];
__device__ __half g_ynl[B_ * L_ * DSSM];

// ---------------- warp-level MMA helpers (arch-neutral PTX) ----------------
__device__ __forceinline__ uint32_t smem_u32(const void* p) {
    uint32_t a;
    asm("{ .reg .u64 t; cvta.to.shared.u64 t, %1; cvt.u32.u64 %0, t; }" : "=r"(a) : "l"(p));
    return a;
}
__device__ __forceinline__ void ldm4(uint32_t* r, uint32_t addr) {
    asm volatile("ldmatrix.sync.aligned.m8n8.x4.shared.b16 {%0,%1,%2,%3}, [%4];"
                 : "=r"(r[0]), "=r"(r[1]), "=r"(r[2]), "=r"(r[3]) : "r"(addr));
}
__device__ __forceinline__ void mma16816h(float* d, const uint32_t* a,
                                          uint32_t b0, uint32_t b1) {
    asm volatile(
        "mma.sync.aligned.m16n8k16.row.col.f32.f16.f16.f32 "
        "{%0,%1,%2,%3}, {%4,%5,%6,%7}, {%8,%9}, {%0,%1,%2,%3};"
        : "+f"(d[0]), "+f"(d[1]), "+f"(d[2]), "+f"(d[3])
        : "r"(a[0]), "r"(a[1]), "r"(a[2]), "r"(a[3]), "r"(b0), "r"(b1));
}
__device__ __forceinline__ void cpasync16(uint32_t dst, const void* src, int sz) {
    asm volatile("cp.async.cg.shared.global [%0], [%1], 16, %2;"
                 :: "r"(dst), "l"(src), "r"(sz) : "memory");
}
#define CP_COMMIT() asm volatile("cp.async.commit_group;" ::: "memory")
#define CP_WAIT0()  asm volatile("cp.async.wait_group 0;" ::: "memory")
#define CP_WAIT1()  asm volatile("cp.async.wait_group 1;" ::: "memory")

// chunk swizzle for 64-byte rows: conflict-free 8-row ldmatrix gathers
#define CSWZ(r, c) ((((c) ^ (((r) >> 1) & 3))) << 4)

// pack two fp32 into fp16x2 hi word + fp16x2 lo-correction word
__device__ __forceinline__ void split2h(float a, float b, uint32_t& hi, uint32_t& lo) {
    __half ha = __float2half_rn(a), hb = __float2half_rn(b);
    __half la = __float2half_rn(a - __half2float(ha));
    __half lb = __float2half_rn(b - __half2float(hb));
    __half2 H{ha, hb}, L{la, lb};
    hi = *(uint32_t*)&H;
    lo = *(uint32_t*)&L;
}
__device__ __forceinline__ uint32_t pack2h(float a, float b) {
    __half2 H{__float2half_rn(a), __float2half_rn(b)};
    return *(uint32_t*)&H;
}

// ---------------- fp32 -> fp16 hi/lo split & single convert ----------------
__global__ __launch_bounds__(256) void split_fp16(const float* __restrict__ src,
                                                  __half* __restrict__ hi,
                                                  __half* __restrict__ lo,
                                                  int n4) {
    int i = blockIdx.x * 256 + threadIdx.x;
    if (i >= n4) return;
    float4 v = ((const float4*)src)[i];
    uint32_t h0, l0, h1, l1;
    split2h(v.x, v.y, h0, l0);
    split2h(v.z, v.w, h1, l1);
    ((uint32_t*)hi)[2 * i + 0] = h0;
    ((uint32_t*)hi)[2 * i + 1] = h1;
    ((uint32_t*)lo)[2 * i + 0] = l0;
    ((uint32_t*)lo)[2 * i + 1] = l1;
}
__global__ __launch_bounds__(256) void cvt_fp16(const float* __restrict__ src,
                                                __half* __restrict__ dst, int n4) {
    int i = blockIdx.x * 256 + threadIdx.x;
    if (i >= n4) return;
    float4 v = ((const float4*)src)[i];
    ((uint32_t*)dst)[2 * i + 0] = pack2h(v.x, v.y);
    ((uint32_t*)dst)[2 * i + 1] = pack2h(v.z, v.w);
}

// ---------------- fp16 one-sided-split HMMA GEMM: C = A @ B^T -------------
#define GM_SMEM (3 * 24576)

__global__ __launch_bounds__(256, 2) void gemm_mma_f16(const __half* __restrict__ Ah,
                                                       const __half* __restrict__ Al,
                                                       const __half* __restrict__ Bh,
                                                       float* __restrict__ C,
                                                       int M, int N, int K, int ldc) {
    extern __shared__ __align__(1024) char sm[];
    const int tid = threadIdx.x;
    const int m0 = blockIdx.y * 128, n0 = blockIdx.x * 128;
    const uint32_t sb0 = smem_u32(sm);
    const int warp = tid >> 5, lane = tid & 31;
    const int warp_m = warp & 3, warp_n = warp >> 2;
    const int KT = K >> 5;

    float acc[2][8][4];
#pragma unroll
    for (int a = 0; a < 2; a++)
#pragma unroll
        for (int b = 0; b < 8; b++)
#pragma unroll
            for (int c = 0; c < 4; c++) acc[a][b][c] = 0.f;

    auto load_stage = [&](int kt, int s) {
        const uint32_t sb = sb0 + s * 24576;
        const int k0 = kt << 5;
#pragma unroll
        for (int ii = 0; ii < 2; ii++) {
            const int i = tid + ii * 256;
            const int r = i >> 2, c = i & 3;
            const uint32_t sw = (uint32_t)(r * 64) + CSWZ(r, c);
            const size_t ga = (size_t)(m0 + r) * K + k0 + c * 8;
            cpasync16(sb + sw, Ah + ga, 16);
            cpasync16(sb + 8192 + sw, Al + ga, 16);
            const int rb = (n0 + r < N) ? (n0 + r) : (N - 1);
            const int bs = (n0 + r < N) ? 16 : 0;
            const size_t gb = (size_t)rb * K + k0 + c * 8;
            cpasync16(sb + 16384 + sw, Bh + gb, bs);
        }
    };

    load_stage(0, 0);
    CP_COMMIT();
    if (KT > 1) {
        load_stage(1, 1);
        CP_COMMIT();
    }

    const int lrow = (lane & 7) + ((lane >> 3) & 1) * 8;
    const int lhalf = lane >> 4;

    for (int kt = 0; kt < KT; kt++) {
        if (kt + 1 < KT) CP_WAIT1(); else CP_WAIT0();
        __syncthreads();
        if (kt + 2 < KT) {
            load_stage(kt + 2, (kt + 2) % 3);
            CP_COMMIT();
        }

        const uint32_t sb = sb0 + (kt % 3) * 24576;
#pragma unroll
        for (int ki = 0; ki < 2; ki++) {
            const int chunk = ki * 2 + lhalf;
            uint32_t ah[2][4], al[2][4];
#pragma unroll
            for (int mi = 0; mi < 2; mi++) {
                const int r = warp_m * 32 + mi * 16 + lrow;
                const uint32_t off = (uint32_t)(r * 64) + CSWZ(r, chunk);
                ldm4(ah[mi], sb + off);
                ldm4(al[mi], sb + 8192 + off);
            }
            uint32_t bh[4][4];
#pragma unroll
            for (int nj = 0; nj < 4; nj++) {
                const int r = warp_n * 64 + nj * 16 + lrow;
                const uint32_t off = (uint32_t)(r * 64) + CSWZ(r, chunk);
                ldm4(bh[nj], sb + 16384 + off);
            }
#pragma unroll
            for (int mi = 0; mi < 2; mi++)
#pragma unroll
                for (int nj = 0; nj < 8; nj++) {
                    const int g = nj >> 1, h = nj & 1;
                    mma16816h(acc[mi][nj], ah[mi], bh[g][h], bh[g][h + 2]);
                    mma16816h(acc[mi][nj], al[mi], bh[g][h], bh[g][h + 2]);
                }
        }
    }

#pragma unroll
    for (int mi = 0; mi < 2; mi++)
#pragma unroll
        for (int nj = 0; nj < 8; nj++) {
            const int row = m0 + warp_m * 32 + mi * 16 + (lane >> 2);
            const int col = n0 + warp_n * 64 + nj * 8 + (lane & 3) * 2;
            if (col < N) {
                float2 v0 = make_float2(acc[mi][nj][0], acc[mi][nj][1]);
                float2 v1 = make_float2(acc[mi][nj][2], acc[mi][nj][3]);
                *(float2*)&C[(size_t)row * ldc + col] = v0;
                *(float2*)&C[(size_t)(row + 8) * ldc + col] = v1;
            }
        }
}

// ---------------- exact fp32 dt: softplus(u @ W_dt^T + bias) -------------
// 256 CTAs x 16 rows for full-chip BW.
__global__ __launch_bounds__(256) void kernel_dt(const float* __restrict__ u,
                                                 const float* __restrict__ W_in,
                                                 const float* __restrict__ dtb) {
    __shared__ float ush[16 * 68];
    __shared__ float wsh[32 * 68];
    const int tid = threadIdx.x;
    const int row0 = blockIdx.x * 16;
    const int col = tid & 31, r0 = (tid >> 5) * 2;
    float acc[2] = {0.f, 0.f};

    for (int k0 = 0; k0 < DM; k0 += 64) {
        {
            const int i = tid;                       // 256 = 16*16
            const int r = i >> 4, c = (i & 15) * 4;
            *(float4*)&ush[r * 68 + c] = *(const float4*)&u[(size_t)(row0 + r) * DM + k0 + c];
        }
#pragma unroll
        for (int ii = 0; ii < 2; ii++) {
            const int i = tid + ii * 256;
            const int r = i >> 4, c = (i & 15) * 4;
            *(float4*)&wsh[r * 68 + c] =
                *(const float4*)&W_in[(size_t)(NZX + r) * DM + k0 + c];
        }
        __syncthreads();
#pragma unroll 8
        for (int k = 0; k < 64; k++) {
            const float w = wsh[col * 68 + k];
            acc[0] += ush[(r0 + 0) * 68 + k] * w;
            acc[1] += ush[(r0 + 1) * 68 + k] * w;
        }
        __syncthreads();
    }
    const float bias = dtb[col];
#pragma unroll
    for (int j = 0; j < 2; j++) {
        float x = acc[j] + bias;
        g_dt[(row0 + r0 + j) * NH + col] = (x > 20.f) ? x : log1pf(expf(x));
    }
}

// ---------------- tree conv + silu ----------------
__global__ __launch_bounds__(256) void kernel_conv(const int* __restrict__ cidx,
                                                   const float* __restrict__ cw,
                                                   const float* __restrict__ cb) {
    const int bt = blockIdx.x;           // b*L_ + t
    const int b = bt / L_, t = bt - b * L_;
    const int tid = threadIdx.x;

    __shared__ int idx[4];
    if (tid < 4) idx[tid] = cidx[(size_t)b * 4 * L_ + 4 * t + tid];
    __syncthreads();
    const int i0 = idx[0], i1 = idx[1], i2 = idx[2], i3 = idx[3];

    for (int c = tid; c < CD; c += 256) {
        float acc = cb[c];
        const float* w = cw + c * 4;
        if (i0) acc += g_zx[(size_t)(b * L_ + i0 - 1) * NZX + DSSM + c] * w[0];
        if (i1) acc += g_zx[(size_t)(b * L_ + i1 - 1) * NZX + DSSM + c] * w[1];
        if (i2) acc += g_zx[(size_t)(b * L_ + i2 - 1) * NZX + DSSM + c] * w[2];
        if (i3) acc += g_zx[(size_t)(b * L_ + i3 - 1) * NZX + DSSM + c] * w[3];
        g_xBC[(size_t)bt * CD + c] = acc / (1.f + __expf(-acc));   // silu
    }
}

// ---------------- per-(b,c,h) inclusive cumsum of dt*A ----------------
__global__ __launch_bounds__(256) void kernel_cumA(const float* __restrict__ A_log) {
    const int blk = blockIdx.x;                 // (b*NC+c)*NH + h
    const int h = blk & (NH - 1);
    const int bc = blk / NH;
    const int b = bc / NC, c = bc - b * NC;
    const int t = threadIdx.x;
    const float Ah = -expf(A_log[h]);
    const int l = b * L_ + c * CH + t;
    __shared__ float s[CH];
    s[t] = g_dt[l * NH + h] * Ah;
    __syncthreads();
    for (int off = 1; off < CH; off <<= 1) {
        float add = (t >= off) ? s[t - off] : 0.f;
        __syncthreads();
        s[t] += add;
        __syncthreads();
    }
    g_cumA[blk * CH + t] = s[t];
}

// ---------------- G = C @ B^T per (b,chunk): lower-triangle blocks only --
__global__ void kernel_G() {
    const int bc = blockIdx.z;                 // b*NC + c
    const int t0 = blockIdx.y * 16, s0 = blockIdx.x * 16;
    if (t0 + 16 <= s0) return;                 // upper triangle never read
    const int tx = threadIdx.x, ty = threadIdx.y;
    const int tid = ty * 16 + tx;
    __shared__ float Cs[16][129];
    __shared__ float Bs[16][129];
    const int b = bc / NC, c = bc - b * NC;
    const int base_l = b * L_ + c * CH;
    for (int i = tid; i < 16 * 128; i += 256) {
        int row = i >> 7, n = i & 127;
        Cs[row][n] = g_xBC[(size_t)(base_l + t0 + row) * CD + DSSM + DS + n];
        Bs[row][n] = g_xBC[(size_t)(base_l + s0 + row) * CD + DSSM + n];
    }
    __syncthreads();
    float acc = 0.f;
#pragma unroll 8
    for (int n = 0; n < 128; n++) acc += Cs[ty][n] * Bs[tx][n];
    g_G[((size_t)bc * CH + t0 + ty) * CH + s0 + tx] = acc;
}

// ---------------- states on fp16 HMMA: S[p,n] = sum_s ws[s]*x[s,p]*B[s,n]
// A = x*ws split fp16 hi/lo (exact), B single fp16. 2 MMAs.
#define ST_CUMA 0
#define ST_WS   1024
#define ST_A    2048
#define ST_ALO  6144
#define ST_B    10240                    // 8KB
#define ST_BSTG 18432                    // [32][129] fp32 = 16512 B
#define ST_XSTG 34944                    // [32][65]  fp32 = 8320 B
#define ST_SMEM 43264

__global__ __launch_bounds__(256) void kernel_states_mma() {
    extern __shared__ __align__(1024) char sm[];
    const int blk = blockIdx.x;
    const int h = blk & (NH - 1);
    const int bc = blk / NH;
    const int b = bc / NC, c = bc - b * NC;
    const int tid = threadIdx.x;
    const int base_l = b * L_ + c * CH;
    const uint32_t sb = smem_u32(sm);
    float* cumA_sh = (float*)(sm + ST_CUMA);
    float* ws_sh = (float*)(sm + ST_WS);
    float* Bstg = (float*)(sm + ST_BSTG);
    float* xstg = (float*)(sm + ST_XSTG);

    cumA_sh[tid] = g_cumA[blk * CH + tid];
    __syncthreads();
    ws_sh[tid] = g_dt[(base_l + tid) * NH + h] * __expf(cumA_sh[CH - 1] - cumA_sh[tid]);
    __syncthreads();

    const int warp = tid >> 5, lane = tid & 31;
    const int warp_m = warp & 1, warp_n = warp >> 1;
    const int lrow = (lane & 7) + ((lane >> 3) & 1) * 8;
    const int lhalf = lane >> 4;

    float acc[2][4][4];
#pragma unroll
    for (int a = 0; a < 2; a++)
#pragma unroll
        for (int bq = 0; bq < 4; bq++)
#pragma unroll
            for (int cq = 0; cq < 4; cq++) acc[a][bq][cq] = 0.f;

    for (int s0 = 0; s0 < CH; s0 += 32) {
#pragma unroll
        for (int ii = 0; ii < 16; ii++) {
            const int i = tid + ii * 256;
            const int s = i >> 7, n = i & 127;
            Bstg[s * 129 + n] = g_xBC[(size_t)(base_l + s0 + s) * CD + DSSM + n];
        }
#pragma unroll
        for (int ii = 0; ii < 8; ii++) {
            const int i = tid + ii * 256;
            const int s = i >> 6, p = i & 63;
            xstg[s * 65 + p] = g_xBC[(size_t)(base_l + s0 + s) * CD + h * HD + p];
        }
        __syncthreads();
#pragma unroll
        for (int jj = 0; jj < 8; jj++) {
            const int j = tid + jj * 256;              // 2048
            const int n = j >> 4, sl = (j & 15) * 2;
            const uint32_t a = (uint32_t)(n * 64) + CSWZ(n, sl >> 3) + (sl & 7) * 2;
            *(uint32_t*)(sm + ST_B + a) = pack2h(Bstg[sl * 129 + n], Bstg[(sl + 1) * 129 + n]);
        }
#pragma unroll
        for (int jj = 0; jj < 4; jj++) {
            const int j = tid + jj * 256;              // 1024
            const int p = j >> 4, sl = (j & 15) * 2;
            uint32_t hi, lo;
            split2h(xstg[sl * 65 + p] * ws_sh[s0 + sl],
                    xstg[(sl + 1) * 65 + p] * ws_sh[s0 + sl + 1], hi, lo);
            const uint32_t a = (uint32_t)(p * 64) + CSWZ(p, sl >> 3) + (sl & 7) * 2;
            *(uint32_t*)(sm + ST_A + a) = hi;
            *(uint32_t*)(sm + ST_ALO + a) = lo;
        }
        __syncthreads();
#pragma unroll
        for (int ki = 0; ki < 2; ki++) {
            const int chunk = ki * 2 + lhalf;
            uint32_t ah[2][4], al[2][4];
#pragma unroll
            for (int mi = 0; mi < 2; mi++) {
                const int r = warp_m * 32 + mi * 16 + lrow;
                const uint32_t off = (uint32_t)(r * 64) + CSWZ(r, chunk);
                ldm4(ah[mi], sb + ST_A + off);
                ldm4(al[mi], sb + ST_ALO + off);
            }
            uint32_t bh[2][4];
#pragma unroll
            for (int nj = 0; nj < 2; nj++) {
                const int r = warp_n * 32 + nj * 16 + lrow;
                const uint32_t off = (uint32_t)(r * 64) + CSWZ(r, chunk);
                ldm4(bh[nj], sb + ST_B + off);
            }
#pragma unroll
            for (int mi = 0; mi < 2; mi++)
#pragma unroll
                for (int nj = 0; nj < 4; nj++) {
                    const int g = nj >> 1, hh = nj & 1;
                    mma16816h(acc[mi][nj], ah[mi], bh[g][hh], bh[g][hh + 2]);
                    mma16816h(acc[mi][nj], al[mi], bh[g][hh], bh[g][hh + 2]);
                }
        }
        __syncthreads();
    }

#pragma unroll
    for (int mi = 0; mi < 2; mi++)
#pragma unroll
        for (int nj = 0; nj < 4; nj++) {
            const int row = warp_m * 32 + mi * 16 + (lane >> 2);
            const int col = warp_n * 32 + nj * 8 + (lane & 3) * 2;
            float* dst = &g_states[(size_t)blk * HD * DS + (size_t)row * DS + col];
            *(float2*)dst = make_float2(acc[mi][nj][0], acc[mi][nj][1]);
            *(float2*)(dst + 8 * DS) = make_float2(acc[mi][nj][2], acc[mi][nj][3]);
        }
}

// ---------------- inter-chunk recurrence (sequential over chunks) --------
__global__ __launch_bounds__(256) void kernel_scan() {
    const int b = blockIdx.x >> 5;
    const int h = blockIdx.x & 31;
    const int tid = threadIdx.x;
    float4 prev[8];
#pragma unroll
    for (int i = 0; i < 8; i++) prev[i] = make_float4(0.f, 0.f, 0.f, 0.f);
    for (int c = 0; c < NC; c++) {
        int blk = (b * NC + c) * NH + h;
        float cd = __expf(g_cumA[blk * CH + CH - 1]);
        const float4* st = (const float4*)&g_states[(size_t)blk * HD * DS];
        float4* pv = (float4*)&g_prev[(size_t)blk * HD * DS];
#pragma unroll
        for (int i = 0; i < 8; i++) {
            float4 s = st[tid + i * 256];
            float4 pr = prev[i];
            pv[tid + i * 256] = pr;
            prev[i] = make_float4(pr.x * cd + s.x, pr.y * cd + s.y,
                                  pr.z * cd + s.z, pr.w * cd + s.w);
        }
    }
}

// ---------------- fused Yd + Yoff + D*x on fp16 HMMA ---------------------
// A = W split fp16 hi/lo (exact), B = xT / prev single fp16. 2 MMAs.
#define YO_CUMA  0
#define YO_DT    1024
#define YO_EA    2048
#define YO_W     3072                    // 16KB [256][64B]
#define YO_WLO   19456                   // 16KB
#define YO_XT    35840                   // 4KB [64][64B]
#define YO_STAGE 39936                   // [32][65] fp32 = 8320 B
#define YO_SMEM  48256

__global__ __launch_bounds__(256) void kernel_ydoff_mma(const float* __restrict__ Dv) {
    extern __shared__ __align__(1024) char sm[];
    const int blk = blockIdx.x;
    const int h = blk & (NH - 1);
    const int bc = blk / NH;
    const int b = bc / NC, c = bc - b * NC;
    const int tid = threadIdx.x;
    const int base_l = b * L_ + c * CH;
    const uint32_t sb = smem_u32(sm);
    float* cumA_sh = (float*)(sm + YO_CUMA);
    float* dt_sh = (float*)(sm + YO_DT);
    float* eA_sh = (float*)(sm + YO_EA);
    float* stg = (float*)(sm + YO_STAGE);
    const float* Gb = g_G + (size_t)bc * CH * CH;

    cumA_sh[tid] = g_cumA[blk * CH + tid];
    dt_sh[tid] = g_dt[(base_l + tid) * NH + h];
    __syncthreads();
    eA_sh[tid] = __expf(cumA_sh[tid]);
    __syncthreads();

    const int warp = tid >> 5, lane = tid & 31;
    const int lrow = (lane & 7) + ((lane >> 3) & 1) * 8;
    const int lhalf = lane >> 4;
    const int rb0 = warp * 16;
    const int rb1 = 240 - warp * 16;

    float acc[2][8][4];
#pragma unroll
    for (int a = 0; a < 2; a++)
#pragma unroll
        for (int bq = 0; bq < 8; bq++)
#pragma unroll
            for (int cq = 0; cq < 4; cq++) acc[a][bq][cq] = 0.f;

    // ---- phase 1: Yd over s-chunks (triangular) ----
    for (int s0 = 0; s0 < CH; s0 += 32) {
#pragma unroll
        for (int ii = 0; ii < 8; ii++) {
            const int i = tid + ii * 256;
            const int s = i >> 6, p = i & 63;
            stg[s * 65 + p] = g_xBC[(size_t)(base_l + s0 + s) * CD + h * HD + p];
        }
        __syncthreads();
        // W rows t >= s0 only (rows < s0 are never read by active slabs)
        const int nent = (CH - s0) * 16;
        for (int j = tid; j < nent; j += 256) {
            const int t = s0 + (j >> 4), sl = (j & 15) * 2;
            const int sg = s0 + sl;
            const float cat = cumA_sh[t];
            float w0 = (t >= sg) ? Gb[t * CH + sg] * __expf(cat - cumA_sh[sg]) * dt_sh[sg] : 0.f;
            float w1 = (t >= sg + 1) ? Gb[t * CH + sg + 1] * __expf(cat - cumA_sh[sg + 1]) * dt_sh[sg + 1] : 0.f;
            uint32_t hi, lo;
            split2h(w0, w1, hi, lo);
            const uint32_t a = (uint32_t)(t * 64) + CSWZ(t, sl >> 3) + (sl & 7) * 2;
            *(uint32_t*)(sm + YO_W + a) = hi;
            *(uint32_t*)(sm + YO_WLO + a) = lo;
        }
        // xT[p][sl] single fp16
#pragma unroll
        for (int jj = 0; jj < 4; jj++) {
            const int j = tid + jj * 256;              // 1024
            const int p = j >> 4, sl = (j & 15) * 2;
            const uint32_t a = (uint32_t)(p * 64) + CSWZ(p, sl >> 3) + (sl & 7) * 2;
            *(uint32_t*)(sm + YO_XT + a) = pack2h(stg[sl * 65 + p], stg[(sl + 1) * 65 + p]);
        }
        __syncthreads();
        const bool act0 = (rb0 + 16 > s0);
        const bool act1 = (rb1 + 16 > s0);
        if (act0 || act1) {
#pragma unroll
            for (int ki = 0; ki < 2; ki++) {
                const int chunk = ki * 2 + lhalf;
                uint32_t bh[4][4];
#pragma unroll
                for (int nj = 0; nj < 4; nj++) {
                    const int r = nj * 16 + lrow;
                    const uint32_t off = (uint32_t)(r * 64) + CSWZ(r, chunk);
                    ldm4(bh[nj], sb + YO_XT + off);
                }
#pragma unroll
                for (int mi = 0; mi < 2; mi++) {
                    if (mi == 0 ? !act0 : !act1) continue;
                    const int r = (mi ? rb1 : rb0) + lrow;
                    const uint32_t off = (uint32_t)(r * 64) + CSWZ(r, chunk);
                    uint32_t ah[4], al[4];
                    ldm4(ah, sb + YO_W + off);
                    ldm4(al, sb + YO_WLO + off);
#pragma unroll
                    for (int nj = 0; nj < 8; nj++) {
                        const int g = nj >> 1, hh = nj & 1;
                        mma16816h(acc[mi][nj], ah, bh[g][hh], bh[g][hh + 2]);
                        mma16816h(acc[mi][nj], al, bh[g][hh], bh[g][hh + 2]);
                    }
                }
            }
        }
        __syncthreads();
    }

    // ---- phase 2: Yoff over n-chunks (dense) ----
    const float* prev_base = &g_prev[(size_t)blk * HD * DS];
    for (int n0 = 0; n0 < DS; n0 += 32) {
#pragma unroll
        for (int jj = 0; jj < 16; jj++) {
            const int j = tid + jj * 256;              // 4096
            const int t = j >> 4, nl = (j & 15) * 2;
            const float ea = eA_sh[t];
            const float* cp = &g_xBC[(size_t)(base_l + t) * CD + DSSM + DS + n0 + nl];
            uint32_t hi, lo;
            split2h(cp[0] * ea, cp[1] * ea, hi, lo);
            const uint32_t a = (uint32_t)(t * 64) + CSWZ(t, nl >> 3) + (nl & 7) * 2;
            *(uint32_t*)(sm + YO_W + a) = hi;
            *(uint32_t*)(sm + YO_WLO + a) = lo;
        }
#pragma unroll
        for (int jj = 0; jj < 4; jj++) {
            const int j = tid + jj * 256;              // 1024
            const int p = j >> 4, nl = (j & 15) * 2;
            const float* pp = &prev_base[(size_t)p * DS + n0 + nl];
            const uint32_t a = (uint32_t)(p * 64) + CSWZ(p, nl >> 3) + (nl & 7) * 2;
            *(uint32_t*)(sm + YO_XT + a) = pack2h(pp[0], pp[1]);
        }
        __syncthreads();
#pragma unroll
        for (int ki = 0; ki < 2; ki++) {
            const int chunk = ki * 2 + lhalf;
            uint32_t bh[4][4];
#pragma unroll
            for (int nj = 0; nj < 4; nj++) {
                const int r = nj * 16 + lrow;
                const uint32_t off = (uint32_t)(r * 64) + CSWZ(r, chunk);
                ldm4(bh[nj], sb + YO_XT + off);
            }
#pragma unroll
            for (int mi = 0; mi < 2; mi++) {
                const int r = (mi ? rb1 : rb0) + lrow;
                const uint32_t off = (uint32_t)(r * 64) + CSWZ(r, chunk);
                uint32_t ah[4], al[4];
                ldm4(ah, sb + YO_W + off);
                ldm4(al, sb + YO_WLO + off);
#pragma unroll
                for (int nj = 0; nj < 8; nj++) {
                    const int g = nj >> 1, hh = nj & 1;
                    mma16816h(acc[mi][nj], ah, bh[g][hh], bh[g][hh + 2]);
                    mma16816h(acc[mi][nj], al, bh[g][hh], bh[g][hh + 2]);
                }
            }
        }
        __syncthreads();
    }

    // ---- epilogue: + D[h]*x, write Y ----
    const float Dh = Dv[h];
#pragma unroll
    for (int mi = 0; mi < 2; mi++)
#pragma unroll
        for (int nj = 0; nj < 8; nj++) {
            const int row = (mi ? rb1 : rb0) + (lane >> 2);
            const int col = nj * 8 + (lane & 3) * 2;
            const size_t l0 = (size_t)(base_l + row);
            float2 x0 = *(const float2*)&g_xBC[l0 * CD + h * HD + col];
            float2 x1 = *(const float2*)&g_xBC[(l0 + 8) * CD + h * HD + col];
            *(float2*)&g_Y[l0 * DSSM + h * HD + col] =
                make_float2(acc[mi][nj][0] + Dh * x0.x, acc[mi][nj][1] + Dh * x0.y);
            *(float2*)&g_Y[(l0 + 8) * DSSM + h * HD + col] =
                make_float2(acc[mi][nj][2] + Dh * x1.x, acc[mi][nj][3] + Dh * x1.y);
        }
}

// ---------------- gated RMSNorm -> fp16 hi/lo ----------------
__global__ __launch_bounds__(256) void kernel_norm(const float* __restrict__ nw) {
    const int row = blockIdx.x;
    const int tid = threadIdx.x;
    const float* y = &g_Y[(size_t)row * DSSM];
    const float* z = &g_zx[(size_t)row * NZX];  // z = first DSSM cols
    float v[8];
    float sum = 0.f;
#pragma unroll
    for (int i = 0; i < 8; i++) {
        int cc = tid + i * 256;
        float zz = z[cc];
        float vv = y[cc] * (zz / (1.f + __expf(-zz)));
        v[i] = vv;
        sum += vv * vv;
    }
    __shared__ float red[256];
    red[tid] = sum;
    __syncthreads();
    for (int off = 128; off; off >>= 1) {
        if (tid < off) red[tid] += red[tid + off];
        __syncthreads();
    }
    const float scale = rsqrtf(red[0] * (1.f / DSSM) + 1e-5f);
#pragma unroll
    for (int i = 0; i < 8; i++) {
        int cc = tid + i * 256;
        float o = v[i] * scale * nw[cc];
        __half hh = __float2half_rn(o);
        g_ynh[(size_t)row * DSSM + cc] = hh;
        g_ynl[(size_t)row * DSSM + cc] = __float2half_rn(o - __half2float(hh));
    }
}

// ---------------- launch ----------------
extern "C" void kernel_launch(void* const* d_in, const int* in_sizes, int n_in,
                              void* d_out, int out_size) {
    const float* u     = (const float*)d_in[0];
    const int*   cidx  = (const int*)d_in[1];
    const float* W_in  = (const float*)d_in[2];
    const float* cw    = (const float*)d_in[3];
    const float* cb    = (const float*)d_in[4];
    const float* dtb   = (const float*)d_in[5];
    const float* A_log = (const float*)d_in[6];
    const float* Dv    = (const float*)d_in[7];
    const float* nw    = (const float*)d_in[8];
    const float* W_out = (const float*)d_in[9];
    float* out = (float*)d_out;

    float* zx_p;
    __half *uh, *ul, *wih, *woh, *ynh, *ynl;
    cudaGetSymbolAddress((void**)&zx_p, g_zx);
    cudaGetSymbolAddress((void**)&uh, g_uh);
    cudaGetSymbolAddress((void**)&ul, g_ul);
    cudaGetSymbolAddress((void**)&wih, g_wih);
    cudaGetSymbolAddress((void**)&woh, g_woh);
    cudaGetSymbolAddress((void**)&ynh, g_ynh);
    cudaGetSymbolAddress((void**)&ynl, g_ynl);

    cudaFuncSetAttribute(gemm_mma_f16, cudaFuncAttributeMaxDynamicSharedMemorySize, GM_SMEM);
    cudaFuncSetAttribute(kernel_states_mma, cudaFuncAttributeMaxDynamicSharedMemorySize, ST_SMEM);
    cudaFuncSetAttribute(kernel_ydoff_mma, cudaFuncAttributeMaxDynamicSharedMemorySize, YO_SMEM);

    // 0) operand converts + exact fp32 dt
    {
        int n4;
        n4 = (B_ * L_ * DM) / 4;
        split_fp16<<<(n4 + 255) / 256, 256>>>(u, uh, ul, n4);
        n4 = (DIP * DM) / 4;
        cvt_fp16<<<(n4 + 255) / 256, 256>>>(W_in, wih, n4);
        n4 = (DM * DSSM) / 4;
        cvt_fp16<<<(n4 + 255) / 256, 256>>>(W_out, woh, n4);
        kernel_dt<<<(B_ * L_) / 16, 256>>>(u, W_in, dtb);
    }
    // 1) z|xBC = u @ W_in[0:4352]^T   (M=4096, N=4352, K=1024) on fp16 HMMA
    gemm_mma_f16<<<dim3(NZX / 128, (B_ * L_) / 128), 256, GM_SMEM>>>(
        uh, ul, wih, zx_p, B_ * L_, NZX, DM, NZX);
    // 2) tree conv + silu
    kernel_conv<<<B_ * L_, 256>>>(cidx, cw, cb);
    // 3) cumsum(dt*A) per chunk/head
    kernel_cumA<<<B_ * NC * NH, 256>>>(A_log);
    // 4) G = C@B^T per (b,chunk), lower-triangle blocks only
    kernel_G<<<dim3(CH / 16, CH / 16, B_ * NC), dim3(16, 16)>>>();
    // 5) chunk end-states on fp16 HMMA (one-sided split)
    kernel_states_mma<<<B_ * NC * NH, 256, ST_SMEM>>>();
    // 6) inter-chunk scan
    kernel_scan<<<B_ * NH, 256>>>();
    // 7) fused Yd + Yoff + D*x on fp16 HMMA (one-sided split, triangular skip)
    kernel_ydoff_mma<<<B_ * NC * NH, 256, YO_SMEM>>>(Dv);
    // 8) gated RMSNorm -> fp16 hi/lo
    kernel_norm<<<B_ * L_, 256>>>(nw);
    // 9) out = yn @ W_out^T  (M=4096, N=1024, K=2048) on fp16 HMMA
    gemm_mma_f16<<<dim3(DM / 128, (B_ * L_) / 128), 256, GM_SMEM>>>(
        ynh, ynl, woh, out, B_ * L_, DM, DSSM, DM);
}